// round 2
// baseline (speedup 1.0000x reference)
#include <cuda_runtime.h>

// Problem constants
#define Bq    16
#define Sq    2048
#define Dq    1024
#define Hq    16
#define CLIPq 8
#define NCq   256
#define DKq   64
#define NTOK  (Bq*Sq)                 // 32768 tokens
#define NELEM ((size_t)NTOK*Dq)       // 33554432 floats per (B,S,D) buffer

// Scratch: Q,K,V, attn-out, spatial-out, temporal-out  (6 x 134MB = 805MB)
__device__ float g_buf[6ull*33554432ull];

// ---------------------------------------------------------------------------
// FP32 SGEMM: C = A(MxK) @ W(KxN) [+ bias] [+ beta*C]
// BM=128, BN=128, BK=16, 256 threads, 8x8 per-thread microtile.
// M,N,K all multiples of tile sizes here, so no bounds checks.
// ---------------------------------------------------------------------------
#define BM 128
#define BN 128
#define BK 16

__global__ __launch_bounds__(256) void sgemm_kernel(
    const float* __restrict__ A, const float* __restrict__ W,
    const float* __restrict__ bias, float* __restrict__ C,
    int M, int N, int K, int beta)
{
    __shared__ float As[BK][BM];
    __shared__ float Bs[BK][BN];
    const int bm  = blockIdx.y * BM;
    const int bn  = blockIdx.x * BN;
    const int tid = threadIdx.x;
    const int tx  = tid & 15;   // n microtile
    const int ty  = tid >> 4;   // m microtile

    float acc[8][8];
    #pragma unroll
    for (int i = 0; i < 8; i++)
        #pragma unroll
        for (int j = 0; j < 8; j++) acc[i][j] = 0.f;

    for (int k0 = 0; k0 < K; k0 += BK) {
        #pragma unroll
        for (int it = 0; it < 2; it++) {
            int idx = tid + it * 256;            // 0..511
            int r  = idx >> 2, c4 = idx & 3;     // A tile: 128 rows x 4 float4
            float4 a = *(const float4*)&A[(size_t)(bm + r) * K + k0 + c4 * 4];
            As[c4*4+0][r] = a.x; As[c4*4+1][r] = a.y;
            As[c4*4+2][r] = a.z; As[c4*4+3][r] = a.w;
            int rb = idx >> 5, cb = idx & 31;    // B tile: 16 rows x 32 float4
            *(float4*)&Bs[rb][cb*4] =
                *(const float4*)&W[(size_t)(k0 + rb) * N + bn + cb * 4];
        }
        __syncthreads();
        #pragma unroll
        for (int kk = 0; kk < BK; kk++) {
            float4 a0 = *(float4*)&As[kk][ty*8];
            float4 a1 = *(float4*)&As[kk][ty*8+4];
            float4 b0 = *(float4*)&Bs[kk][tx*8];
            float4 b1 = *(float4*)&Bs[kk][tx*8+4];
            float ra[8] = {a0.x,a0.y,a0.z,a0.w,a1.x,a1.y,a1.z,a1.w};
            float rb[8] = {b0.x,b0.y,b0.z,b0.w,b1.x,b1.y,b1.z,b1.w};
            #pragma unroll
            for (int i = 0; i < 8; i++)
                #pragma unroll
                for (int j = 0; j < 8; j++)
                    acc[i][j] += ra[i] * rb[j];
        }
        __syncthreads();
    }

    #pragma unroll
    for (int i = 0; i < 8; i++) {
        size_t row = (size_t)(bm + ty*8 + i);
        #pragma unroll
        for (int j = 0; j < 8; j += 4) {
            int col = bn + tx*8 + j;
            float4 v = make_float4(acc[i][j], acc[i][j+1], acc[i][j+2], acc[i][j+3]);
            if (bias) {
                v.x += bias[col];   v.y += bias[col+1];
                v.z += bias[col+2]; v.w += bias[col+3];
            }
            float* cp = &C[row * N + col];
            if (beta) {
                float4 o = *(float4*)cp;
                v.x += o.x; v.y += o.y; v.z += o.z; v.w += o.w;
            }
            *(float4*)cp = v;
        }
    }
}

// ---------------------------------------------------------------------------
// Spatial attention: per (b, clip c, half-of-heads): 8x8 attention, dk=64.
// K,V for 8 heads staged in smem (32KB); Q read direct. Softmax without
// max-subtraction (scores are O(1); mathematically identical).
// grid = B*NC*2, 64 threads: thread = (head-in-half, query-row).
// ---------------------------------------------------------------------------
__global__ __launch_bounds__(64) void spatial_attn_kernel(
    const float* __restrict__ Q, const float* __restrict__ K,
    const float* __restrict__ V, const int* __restrict__ mask,
    float* __restrict__ O)
{
    __shared__ float sK[8][512];
    __shared__ float sV[8][512];
    int blk  = blockIdx.x;
    int half = blk & 1;
    int c    = (blk >> 1) & (NCq - 1);
    int b    = blk >> 9;
    size_t base = ((size_t)b * Sq + (size_t)c * CLIPq) * Dq;

    for (int idx = threadIdx.x; idx < 8 * 512 / 4; idx += 64) {
        int r = idx >> 7, c4 = idx & 127;
        size_t g = base + (size_t)r * Dq + half * 512 + c4 * 4;
        *(float4*)&sK[r][c4*4] = *(const float4*)&K[g];
        *(float4*)&sV[r][c4*4] = *(const float4*)&V[g];
    }
    __syncthreads();

    int hp = threadIdx.x >> 3;      // head within half
    int i  = threadIdx.x & 7;       // query row
    int h  = half * 8 + hp;

    float q[64];
    const float* qg = &Q[base + (size_t)i * Dq + h * DKq];
    #pragma unroll
    for (int d = 0; d < 64; d += 4) {
        float4 t = *(const float4*)&qg[d];
        q[d] = t.x; q[d+1] = t.y; q[d+2] = t.z; q[d+3] = t.w;
    }

    float e[8]; float l = 0.f;
    #pragma unroll
    for (int j = 0; j < 8; j++) {
        const float* kr = &sK[j][hp * DKq];
        float s0 = 0.f, s1 = 0.f, s2 = 0.f, s3 = 0.f;
        #pragma unroll
        for (int d = 0; d < 64; d += 4) {
            s0 += q[d]   * kr[d];   s1 += q[d+1] * kr[d+1];
            s2 += q[d+2] * kr[d+2]; s3 += q[d+3] * kr[d+3];
        }
        float s = (s0 + s1 + s2 + s3) * 0.125f;
        float ee = mask[b * Sq + c * CLIPq + j] ? __expf(s) : 0.f;
        e[j] = ee; l += ee;
    }
    float inv = 1.f / l;

    float out[64];
    #pragma unroll
    for (int d = 0; d < 64; d++) out[d] = 0.f;
    #pragma unroll
    for (int j = 0; j < 8; j++) {
        const float* vr = &sV[j][hp * DKq];
        float ej = e[j];
        #pragma unroll
        for (int d = 0; d < 64; d++) out[d] += ej * vr[d];
    }

    float* og = &O[base + (size_t)i * Dq + h * DKq];
    #pragma unroll
    for (int d = 0; d < 64; d += 4) {
        float4 t = make_float4(out[d]*inv, out[d+1]*inv, out[d+2]*inv, out[d+3]*inv);
        *(float4*)&og[d] = t;
    }
}

// ---------------------------------------------------------------------------
// Temporal attention: per (b, clip-pos p, head h): 256x256 attention, dk=64.
// One block per unit, 256 threads = one query row each. K/V tiles (64 rows)
// staged in smem; all threads read the same row => broadcast LDS (free).
// Softmax without max-subtraction; masked keys multiply their exp by 0.
// grid = B*CLIP*H = 2048.
// ---------------------------------------------------------------------------
__global__ __launch_bounds__(256) void temporal_attn_kernel(
    const float* __restrict__ Q, const float* __restrict__ K,
    const float* __restrict__ V, const int* __restrict__ mask,
    float* __restrict__ O)
{
    __shared__ float sK[64][64];
    __shared__ float sV[64][64];
    __shared__ float sM[256];
    int blk = blockIdx.x;
    int h = blk & 15;
    int p = (blk >> 4) & 7;
    int b = blk >> 7;
    int cq = threadIdx.x;

    sM[cq] = mask[b * Sq + cq * CLIPq + p] ? 1.f : 0.f;

    float q[64];
    size_t qbase = ((size_t)b * Sq + (size_t)cq * CLIPq + p) * Dq + h * DKq;
    #pragma unroll
    for (int d = 0; d < 64; d += 4) {
        float4 t = *(const float4*)&Q[qbase + d];
        q[d] = t.x; q[d+1] = t.y; q[d+2] = t.z; q[d+3] = t.w;
    }

    float acc[64];
    #pragma unroll
    for (int d = 0; d < 64; d++) acc[d] = 0.f;
    float l = 0.f;

    for (int t0 = 0; t0 < NCq; t0 += 64) {
        for (int idx = threadIdx.x; idx < 1024; idx += 256) {
            int r = idx >> 4, c4 = idx & 15;
            size_t gb = ((size_t)b * Sq + (size_t)(t0 + r) * CLIPq + p) * Dq
                        + h * DKq + c4 * 4;
            *(float4*)&sK[r][c4*4] = *(const float4*)&K[gb];
            *(float4*)&sV[r][c4*4] = *(const float4*)&V[gb];
        }
        __syncthreads();
        #pragma unroll 4
        for (int j = 0; j < 64; j++) {
            float s0 = 0.f, s1 = 0.f, s2 = 0.f, s3 = 0.f;
            #pragma unroll
            for (int d = 0; d < 64; d += 4) {
                s0 += q[d]   * sK[j][d];   s1 += q[d+1] * sK[j][d+1];
                s2 += q[d+2] * sK[j][d+2]; s3 += q[d+3] * sK[j][d+3];
            }
            float e = __expf((s0 + s1 + s2 + s3) * 0.125f) * sM[t0 + j];
            l += e;
            #pragma unroll
            for (int d = 0; d < 64; d++) acc[d] += e * sV[j][d];
        }
        __syncthreads();
    }

    float inv = 1.f / l;
    #pragma unroll
    for (int d = 0; d < 64; d += 4) {
        float4 t = make_float4(acc[d]*inv, acc[d+1]*inv, acc[d+2]*inv, acc[d+3]*inv);
        *(float4*)&O[qbase + d] = t;
    }
}

// ---------------------------------------------------------------------------
// Launch: 3 QKV GEMMs + attn + O GEMM for each branch, then fuse as two
// K=1024 GEMMs (second accumulates) to avoid materializing the concat.
// ---------------------------------------------------------------------------
extern "C" void kernel_launch(void* const* d_in, const int* in_sizes, int n_in,
                              void* d_out, int out_size)
{
    const float* x      = (const float*)d_in[0];
    const int*   mask   = (const int*)  d_in[1];
    const float* sa_q_w = (const float*)d_in[2];
    const float* sa_q_b = (const float*)d_in[3];
    const float* sa_k_w = (const float*)d_in[4];
    const float* sa_k_b = (const float*)d_in[5];
    const float* sa_v_w = (const float*)d_in[6];
    const float* sa_v_b = (const float*)d_in[7];
    const float* sa_o_w = (const float*)d_in[8];
    const float* sa_o_b = (const float*)d_in[9];
    const float* ta_q_w = (const float*)d_in[10];
    const float* ta_q_b = (const float*)d_in[11];
    const float* ta_k_w = (const float*)d_in[12];
    const float* ta_k_b = (const float*)d_in[13];
    const float* ta_v_w = (const float*)d_in[14];
    const float* ta_v_b = (const float*)d_in[15];
    const float* ta_o_w = (const float*)d_in[16];
    const float* ta_o_b = (const float*)d_in[17];
    const float* fuse_w = (const float*)d_in[18];
    const float* fuse_b = (const float*)d_in[19];
    float* out = (float*)d_out;

    float* buf = nullptr;
    cudaGetSymbolAddress((void**)&buf, g_buf);
    float* bQ = buf;
    float* bK = buf + NELEM;
    float* bV = buf + 2*NELEM;
    float* bA = buf + 3*NELEM;
    float* bS = buf + 4*NELEM;
    float* bT = buf + 5*NELEM;

    dim3 gg(Dq / BN, NTOK / BM);   // (8, 256)

    // Spatial branch
    sgemm_kernel<<<gg, 256>>>(x,  sa_q_w, sa_q_b, bQ, NTOK, Dq, Dq, 0);
    sgemm_kernel<<<gg, 256>>>(x,  sa_k_w, sa_k_b, bK, NTOK, Dq, Dq, 0);
    sgemm_kernel<<<gg, 256>>>(x,  sa_v_w, sa_v_b, bV, NTOK, Dq, Dq, 0);
    spatial_attn_kernel<<<Bq*NCq*2, 64>>>(bQ, bK, bV, mask, bA);
    sgemm_kernel<<<gg, 256>>>(bA, sa_o_w, sa_o_b, bS, NTOK, Dq, Dq, 0);

    // Temporal branch
    sgemm_kernel<<<gg, 256>>>(x,  ta_q_w, ta_q_b, bQ, NTOK, Dq, Dq, 0);
    sgemm_kernel<<<gg, 256>>>(x,  ta_k_w, ta_k_b, bK, NTOK, Dq, Dq, 0);
    sgemm_kernel<<<gg, 256>>>(x,  ta_v_w, ta_v_b, bV, NTOK, Dq, Dq, 0);
    temporal_attn_kernel<<<Bq*CLIPq*Hq, 256>>>(bQ, bK, bV, mask, bA);
    sgemm_kernel<<<gg, 256>>>(bA, ta_o_w, ta_o_b, bT, NTOK, Dq, Dq, 0);

    // Fuse: out = bS @ fuse_w[0:1024] + fuse_b  +  bT @ fuse_w[1024:2048]
    sgemm_kernel<<<gg, 256>>>(bS, fuse_w,                    fuse_b,  out, NTOK, Dq, Dq, 0);
    sgemm_kernel<<<gg, 256>>>(bT, fuse_w + (size_t)Dq * Dq,  nullptr, out, NTOK, Dq, Dq, 1);
}

// round 4
// speedup vs baseline: 2.0192x; 2.0192x over previous
#include <cuda_runtime.h>
#include <cuda_bf16.h>
#include <cstdint>

// Problem constants
#define Bq    16
#define Sq    2048
#define Dq    1024
#define Hq    16
#define CLIPq 8
#define NCq   256
#define DKq   64
#define NTOK  (Bq*Sq)                 // 32768 tokens
#define NELEM ((size_t)NTOK*Dq)       // 33554432 floats per (B,S,D) buffer

// Scratch pool:
//  [0..6)*NELEM fp32 : bQ,bK,bV,bA,bS,bT
//  [6..7)*NELEM fp32 : xHi,xLo   (NELEM bf16 each)
//  [7..8)*NELEM fp32 : aHi,aLo   (NELEM bf16 each)
//  [8..  ]           : weight hi/lo pools (10M bf16 each)
__device__ float g_buf[9ull*33554432ull];

__device__ __forceinline__ uint32_t smem_u32(const void* p) {
    uint32_t a;
    asm("{ .reg .u64 t; cvta.to.shared.u64 t, %1; cvt.u32.u64 %0, t; }"
        : "=r"(a) : "l"(p));
    return a;
}

__device__ __forceinline__ void ldsm4(uint32_t& r0, uint32_t& r1,
                                      uint32_t& r2, uint32_t& r3, uint32_t a) {
    asm volatile("ldmatrix.sync.aligned.m8n8.x4.shared.b16 {%0,%1,%2,%3}, [%4];"
        : "=r"(r0), "=r"(r1), "=r"(r2), "=r"(r3) : "r"(a));
}

__device__ __forceinline__ void mma_bf16(float* c,
    uint32_t a0, uint32_t a1, uint32_t a2, uint32_t a3,
    uint32_t b0, uint32_t b1) {
    asm volatile("mma.sync.aligned.m16n8k16.row.col.f32.bf16.bf16.f32 "
        "{%0,%1,%2,%3}, {%4,%5,%6,%7}, {%8,%9}, {%0,%1,%2,%3};"
        : "+f"(c[0]), "+f"(c[1]), "+f"(c[2]), "+f"(c[3])
        : "r"(a0), "r"(a1), "r"(a2), "r"(a3), "r"(b0), "r"(b1));
}

__device__ __forceinline__ void cp16(uint32_t s, const void* g) {
    asm volatile("cp.async.cg.shared.global [%0], [%1], 16;" :: "r"(s), "l"(g));
}

// ============================================================================
// bf16 3-pass GEMM via mma.sync: C[M,N] = (Ahi+Alo)[M,K] @ (Bhi+Blo)^T[N,K]
// (dropping Alo*Blo), fp32 register accumulation.
// Tile 128x128, BK=32, double-buffered cp.async. 256 threads = 8 warps (2x4),
// warp tile 64x32. SMEM row stride 80B -> ldmatrix conflict-free (5r mod 8).
// ============================================================================
#define TCSTRIDE 80                       // bytes per 32-elem bf16 row (+pad)
#define TCTILE   (128 * TCSTRIDE)         // 10240 B per operand tile
#define TCSTAGE  (4 * TCTILE)             // Ah, Al, Bh, Bl
#define TC_SMEM  (2 * TCSTAGE)            // 81920 B
#define NIT      (Dq / 32)                // 32 K-iterations

__global__ void __launch_bounds__(256, 1) tcgemm_kernel(
    const __nv_bfloat16* __restrict__ Ahi, const __nv_bfloat16* __restrict__ Alo,
    const __nv_bfloat16* __restrict__ Bhi, const __nv_bfloat16* __restrict__ Blo,
    const float* __restrict__ bias, float* __restrict__ C, int beta)
{
    extern __shared__ char smem[];
    const uint32_t sb = smem_u32(smem);
    const int tid  = threadIdx.x;
    const int lane = tid & 31;
    const int wid  = tid >> 5;
    const int wm = (wid >> 2) * 64;       // warp m offset in tile
    const int wn = (wid & 3) * 32;        // warp n offset in tile
    const int bm = blockIdx.y * 128;
    const int bn = blockIdx.x * 128;
    const int K  = Dq;

    const __nv_bfloat16* gptr[4] = {
        Ahi + (size_t)bm * K, Alo + (size_t)bm * K,
        Bhi + (size_t)bn * K, Blo + (size_t)bn * K };

    float acc[4][4][4];
    #pragma unroll
    for (int i = 0; i < 4; i++)
        #pragma unroll
        for (int j = 0; j < 4; j++)
            #pragma unroll
            for (int k = 0; k < 4; k++) acc[i][j][k] = 0.f;

    // ldmatrix per-lane address components
    const int rowA = (lane & 7) + ((lane >> 3) & 1) * 8;  // 0..15
    const int kbA  = (lane >> 4) * 16;                    // 0 or 16 bytes
    const int rowB = (lane & 7) + (lane >> 4) * 8;        // 0..15
    const int kbB  = ((lane >> 3) & 1) * 16;

    // async fill of one stage (BK=32): 4 tiles x 512 16B-chunks
    auto fill = [&](int it, int buf) {
        uint32_t sst = sb + buf * TCSTAGE;
        int k0 = it * 32;
        #pragma unroll
        for (int j = 0; j < 8; j++) {
            int t   = j >> 1;
            int rem = tid + (j & 1) * 256;       // 0..511
            int r   = rem >> 2, c = rem & 3;
            const void* g = gptr[t] + (size_t)r * K + k0 + c * 8;
            cp16(sst + t * TCTILE + r * TCSTRIDE + c * 16, g);
        }
        asm volatile("cp.async.commit_group;" ::: "memory");
    };

    fill(0, 0);

    for (int it = 0; it < NIT; it++) {
        if (it + 1 < NIT) {
            fill(it + 1, (it + 1) & 1);
            asm volatile("cp.async.wait_group 1;" ::: "memory");
        } else {
            asm volatile("cp.async.wait_group 0;" ::: "memory");
        }
        __syncthreads();

        uint32_t sst = sb + (it & 1) * TCSTAGE;
        uint32_t aHiB = sst + 0 * TCTILE + (wm + rowA) * TCSTRIDE + kbA;
        uint32_t aLoB = sst + 1 * TCTILE + (wm + rowA) * TCSTRIDE + kbA;
        uint32_t bHiB = sst + 2 * TCTILE + (wn + rowB) * TCSTRIDE + kbB;
        uint32_t bLoB = sst + 3 * TCTILE + (wn + rowB) * TCSTRIDE + kbB;

        #pragma unroll
        for (int ks = 0; ks < 2; ks++) {
            uint32_t ah[4][4], al[4][4], bh[2][4], bl[2][4];
            #pragma unroll
            for (int mt = 0; mt < 4; mt++) {
                uint32_t off = mt * 16 * TCSTRIDE + ks * 32;
                ldsm4(ah[mt][0], ah[mt][1], ah[mt][2], ah[mt][3], aHiB + off);
                ldsm4(al[mt][0], al[mt][1], al[mt][2], al[mt][3], aLoB + off);
            }
            #pragma unroll
            for (int p = 0; p < 2; p++) {
                uint32_t off = p * 16 * TCSTRIDE + ks * 32;
                ldsm4(bh[p][0], bh[p][1], bh[p][2], bh[p][3], bHiB + off);
                ldsm4(bl[p][0], bl[p][1], bl[p][2], bl[p][3], bLoB + off);
            }
            #pragma unroll
            for (int mt = 0; mt < 4; mt++) {
                #pragma unroll
                for (int nt = 0; nt < 4; nt++) {
                    int p = nt >> 1, hf = (nt & 1) * 2;
                    mma_bf16(acc[mt][nt], ah[mt][0], ah[mt][1], ah[mt][2], ah[mt][3],
                             bh[p][hf], bh[p][hf + 1]);
                    mma_bf16(acc[mt][nt], ah[mt][0], ah[mt][1], ah[mt][2], ah[mt][3],
                             bl[p][hf], bl[p][hf + 1]);
                    mma_bf16(acc[mt][nt], al[mt][0], al[mt][1], al[mt][2], al[mt][3],
                             bh[p][hf], bh[p][hf + 1]);
                }
            }
        }
        __syncthreads();
    }

    // Epilogue: write accumulators
    #pragma unroll
    for (int mt = 0; mt < 4; mt++) {
        #pragma unroll
        for (int nt = 0; nt < 4; nt++) {
            int r0 = bm + wm + mt * 16 + (lane >> 2);
            int c0 = bn + wn + nt * 8 + (lane & 3) * 2;
            #pragma unroll
            for (int hrow = 0; hrow < 2; hrow++) {
                float2 v = make_float2(acc[mt][nt][hrow * 2],
                                       acc[mt][nt][hrow * 2 + 1]);
                if (bias) {
                    v.x += __ldg(&bias[c0]);
                    v.y += __ldg(&bias[c0 + 1]);
                }
                float* cp = C + (size_t)(r0 + hrow * 8) * Dq + c0;
                if (beta) {
                    float2 o = *(float2*)cp;
                    v.x += o.x; v.y += o.y;
                }
                *(float2*)cp = v;
            }
        }
    }
}

// ============================================================================
// fp32 -> bf16 hi/lo split (elementwise)
// ============================================================================
__global__ void __launch_bounds__(256) split_kernel(
    const float* __restrict__ in, __nv_bfloat16* __restrict__ hi,
    __nv_bfloat16* __restrict__ lo, int n4)
{
    int i = blockIdx.x * 256 + threadIdx.x;
    if (i >= n4) return;
    float4 v = ((const float4*)in)[i];
    float f[4] = {v.x, v.y, v.z, v.w};
    ushort4 uh, ul;
    unsigned short* ph = &uh.x;
    unsigned short* pl = &ul.x;
    #pragma unroll
    for (int k = 0; k < 4; k++) {
        __nv_bfloat16 h = __float2bfloat16_rn(f[k]);
        __nv_bfloat16 l = __float2bfloat16_rn(f[k] - __bfloat162float(h));
        ph[k] = __bfloat16_as_ushort(h);
        pl[k] = __bfloat16_as_ushort(l);
    }
    ((ushort4*)hi)[i] = uh;
    ((ushort4*)lo)[i] = ul;
}

// ============================================================================
// Weight transpose + split: W[1024 x 1024] row-major -> out[n][k] = W[k][n]
// ============================================================================
__global__ void __launch_bounds__(256) transpose_split_kernel(
    const float* __restrict__ W, __nv_bfloat16* __restrict__ hi,
    __nv_bfloat16* __restrict__ lo)
{
    __shared__ float t[32][33];
    int bx = blockIdx.x * 32, by = blockIdx.y * 32;
    int tx = threadIdx.x & 31, ty = threadIdx.x >> 5;   // 32 x 8
    #pragma unroll
    for (int j = 0; j < 32; j += 8)
        t[ty + j][tx] = W[(size_t)(by + ty + j) * 1024 + bx + tx];
    __syncthreads();
    #pragma unroll
    for (int j = 0; j < 32; j += 8) {
        float v = t[tx][ty + j];
        __nv_bfloat16 h = __float2bfloat16_rn(v);
        __nv_bfloat16 l = __float2bfloat16_rn(v - __bfloat162float(h));
        size_t o = (size_t)(bx + ty + j) * 1024 + by + tx;
        hi[o] = h; lo[o] = l;
    }
}

// ---------------------------------------------------------------------------
// Spatial attention
// ---------------------------------------------------------------------------
__global__ __launch_bounds__(64) void spatial_attn_kernel(
    const float* __restrict__ Q, const float* __restrict__ K,
    const float* __restrict__ V, const int* __restrict__ mask,
    float* __restrict__ O)
{
    __shared__ float sK[8][512];
    __shared__ float sV[8][512];
    int blk  = blockIdx.x;
    int half = blk & 1;
    int c    = (blk >> 1) & (NCq - 1);
    int b    = blk >> 9;
    size_t base = ((size_t)b * Sq + (size_t)c * CLIPq) * Dq;

    for (int idx = threadIdx.x; idx < 8 * 512 / 4; idx += 64) {
        int r = idx >> 7, c4 = idx & 127;
        size_t g = base + (size_t)r * Dq + half * 512 + c4 * 4;
        *(float4*)&sK[r][c4*4] = *(const float4*)&K[g];
        *(float4*)&sV[r][c4*4] = *(const float4*)&V[g];
    }
    __syncthreads();

    int hp = threadIdx.x >> 3;
    int i  = threadIdx.x & 7;
    int h  = half * 8 + hp;

    float q[64];
    const float* qg = &Q[base + (size_t)i * Dq + h * DKq];
    #pragma unroll
    for (int d = 0; d < 64; d += 4) {
        float4 t = *(const float4*)&qg[d];
        q[d] = t.x; q[d+1] = t.y; q[d+2] = t.z; q[d+3] = t.w;
    }

    float e[8]; float l = 0.f;
    #pragma unroll
    for (int j = 0; j < 8; j++) {
        const float* kr = &sK[j][hp * DKq];
        float s0 = 0.f, s1 = 0.f, s2 = 0.f, s3 = 0.f;
        #pragma unroll
        for (int d = 0; d < 64; d += 4) {
            s0 += q[d]   * kr[d];   s1 += q[d+1] * kr[d+1];
            s2 += q[d+2] * kr[d+2]; s3 += q[d+3] * kr[d+3];
        }
        float s = (s0 + s1 + s2 + s3) * 0.125f;
        float ee = mask[b * Sq + c * CLIPq + j] ? __expf(s) : 0.f;
        e[j] = ee; l += ee;
    }
    float inv = 1.f / l;

    float out[64];
    #pragma unroll
    for (int d = 0; d < 64; d++) out[d] = 0.f;
    #pragma unroll
    for (int j = 0; j < 8; j++) {
        const float* vr = &sV[j][hp * DKq];
        float ej = e[j];
        #pragma unroll
        for (int d = 0; d < 64; d++) out[d] += ej * vr[d];
    }

    float* og = &O[base + (size_t)i * Dq + h * DKq];
    #pragma unroll
    for (int d = 0; d < 64; d += 4) {
        float4 t = make_float4(out[d]*inv, out[d+1]*inv, out[d+2]*inv, out[d+3]*inv);
        *(float4*)&og[d] = t;
    }
}

// ---------------------------------------------------------------------------
// Temporal attention
// ---------------------------------------------------------------------------
__global__ __launch_bounds__(256) void temporal_attn_kernel(
    const float* __restrict__ Q, const float* __restrict__ K,
    const float* __restrict__ V, const int* __restrict__ mask,
    float* __restrict__ O)
{
    __shared__ float sK[64][64];
    __shared__ float sV[64][64];
    __shared__ float sM[256];
    int blk = blockIdx.x;
    int h = blk & 15;
    int p = (blk >> 4) & 7;
    int b = blk >> 7;
    int cq = threadIdx.x;

    sM[cq] = mask[b * Sq + cq * CLIPq + p] ? 1.f : 0.f;

    float q[64];
    size_t qbase = ((size_t)b * Sq + (size_t)cq * CLIPq + p) * Dq + h * DKq;
    #pragma unroll
    for (int d = 0; d < 64; d += 4) {
        float4 t = *(const float4*)&Q[qbase + d];
        q[d] = t.x; q[d+1] = t.y; q[d+2] = t.z; q[d+3] = t.w;
    }

    float acc[64];
    #pragma unroll
    for (int d = 0; d < 64; d++) acc[d] = 0.f;
    float l = 0.f;

    for (int t0 = 0; t0 < NCq; t0 += 64) {
        for (int idx = threadIdx.x; idx < 1024; idx += 256) {
            int r = idx >> 4, c4 = idx & 15;
            size_t gb = ((size_t)b * Sq + (size_t)(t0 + r) * CLIPq + p) * Dq
                        + h * DKq + c4 * 4;
            *(float4*)&sK[r][c4*4] = *(const float4*)&K[gb];
            *(float4*)&sV[r][c4*4] = *(const float4*)&V[gb];
        }
        __syncthreads();
        #pragma unroll 4
        for (int j = 0; j < 64; j++) {
            float s0 = 0.f, s1 = 0.f, s2 = 0.f, s3 = 0.f;
            #pragma unroll
            for (int d = 0; d < 64; d += 4) {
                s0 += q[d]   * sK[j][d];   s1 += q[d+1] * sK[j][d+1];
                s2 += q[d+2] * sK[j][d+2]; s3 += q[d+3] * sK[j][d+3];
            }
            float e = __expf((s0 + s1 + s2 + s3) * 0.125f) * sM[t0 + j];
            l += e;
            #pragma unroll
            for (int d = 0; d < 64; d++) acc[d] += e * sV[j][d];
        }
        __syncthreads();
    }

    float inv = 1.f / l;
    #pragma unroll
    for (int d = 0; d < 64; d += 4) {
        float4 t = make_float4(acc[d]*inv, acc[d+1]*inv, acc[d+2]*inv, acc[d+3]*inv);
        *(float4*)&O[qbase + d] = t;
    }
}

// ---------------------------------------------------------------------------
// Launch
// ---------------------------------------------------------------------------
extern "C" void kernel_launch(void* const* d_in, const int* in_sizes, int n_in,
                              void* d_out, int out_size)
{
    const float* x      = (const float*)d_in[0];
    const int*   mask   = (const int*)  d_in[1];
    const float* wsrc[10] = {
        (const float*)d_in[2],  // sa_q_w
        (const float*)d_in[4],  // sa_k_w
        (const float*)d_in[6],  // sa_v_w
        (const float*)d_in[8],  // sa_o_w
        (const float*)d_in[10], // ta_q_w
        (const float*)d_in[12], // ta_k_w
        (const float*)d_in[14], // ta_v_w
        (const float*)d_in[16], // ta_o_w
        (const float*)d_in[18],                          // fuse_w rows 0..1023
        (const float*)d_in[18] + (size_t)1024 * 1024     // fuse_w rows 1024..2047
    };
    const float* sa_q_b = (const float*)d_in[3];
    const float* sa_k_b = (const float*)d_in[5];
    const float* sa_v_b = (const float*)d_in[7];
    const float* sa_o_b = (const float*)d_in[9];
    const float* ta_q_b = (const float*)d_in[11];
    const float* ta_k_b = (const float*)d_in[13];
    const float* ta_v_b = (const float*)d_in[15];
    const float* ta_o_b = (const float*)d_in[17];
    const float* fuse_b = (const float*)d_in[19];
    float* out = (float*)d_out;

    float* base = nullptr;
    cudaGetSymbolAddress((void**)&base, g_buf);
    float* bQ = base;
    float* bK = base + NELEM;
    float* bV = base + 2*NELEM;
    float* bA = base + 3*NELEM;
    float* bS = base + 4*NELEM;
    float* bT = base + 5*NELEM;
    __nv_bfloat16* xHi = (__nv_bfloat16*)(base + 6*NELEM);
    __nv_bfloat16* xLo = xHi + NELEM;
    __nv_bfloat16* aHi = (__nv_bfloat16*)(base + 7*NELEM);
    __nv_bfloat16* aLo = aHi + NELEM;
    __nv_bfloat16* wHi = (__nv_bfloat16*)(base + 8*NELEM);
    __nv_bfloat16* wLo = wHi + (size_t)10 * 1024 * 1024;

    cudaFuncSetAttribute(tcgemm_kernel,
        cudaFuncAttributeMaxDynamicSharedMemorySize, TC_SMEM);

    const int n4 = (int)(NELEM / 4);
    const int splitBlocks = (n4 + 255) / 256;
    dim3 tgrid(32, 32), tblk(256);
    dim3 ggrid(Dq / 128, NTOK / 128);   // (8, 256)

    // Prep: split x, transpose+split all weights
    split_kernel<<<splitBlocks, 256>>>(x, xHi, xLo, n4);
    for (int i = 0; i < 10; i++)
        transpose_split_kernel<<<tgrid, tblk>>>(wsrc[i],
            wHi + (size_t)i * 1024 * 1024, wLo + (size_t)i * 1024 * 1024);

    #define WT(i) (wHi + (size_t)(i)*1024*1024), (wLo + (size_t)(i)*1024*1024)

    // Spatial branch
    tcgemm_kernel<<<ggrid, 256, TC_SMEM>>>(xHi, xLo, WT(0), sa_q_b, bQ, 0);
    tcgemm_kernel<<<ggrid, 256, TC_SMEM>>>(xHi, xLo, WT(1), sa_k_b, bK, 0);
    tcgemm_kernel<<<ggrid, 256, TC_SMEM>>>(xHi, xLo, WT(2), sa_v_b, bV, 0);
    spatial_attn_kernel<<<Bq*NCq*2, 64>>>(bQ, bK, bV, mask, bA);
    split_kernel<<<splitBlocks, 256>>>(bA, aHi, aLo, n4);
    tcgemm_kernel<<<ggrid, 256, TC_SMEM>>>(aHi, aLo, WT(3), sa_o_b, bS, 0);

    // Temporal branch
    tcgemm_kernel<<<ggrid, 256, TC_SMEM>>>(xHi, xLo, WT(4), ta_q_b, bQ, 0);
    tcgemm_kernel<<<ggrid, 256, TC_SMEM>>>(xHi, xLo, WT(5), ta_k_b, bK, 0);
    tcgemm_kernel<<<ggrid, 256, TC_SMEM>>>(xHi, xLo, WT(6), ta_v_b, bV, 0);
    temporal_attn_kernel<<<Bq*CLIPq*Hq, 256>>>(bQ, bK, bV, mask, bA);
    split_kernel<<<splitBlocks, 256>>>(bA, aHi, aLo, n4);
    tcgemm_kernel<<<ggrid, 256, TC_SMEM>>>(aHi, aLo, WT(7), ta_o_b, bT, 0);

    // Fuse: out = bS @ fuse_w[0:1024] + fuse_b + bT @ fuse_w[1024:2048]
    split_kernel<<<splitBlocks, 256>>>(bS, aHi, aLo, n4);
    tcgemm_kernel<<<ggrid, 256, TC_SMEM>>>(aHi, aLo, WT(8), fuse_b, out, 0);
    split_kernel<<<splitBlocks, 256>>>(bT, aHi, aLo, n4);
    tcgemm_kernel<<<ggrid, 256, TC_SMEM>>>(aHi, aLo, WT(9), nullptr, out, 1);
}

// round 5
// speedup vs baseline: 2.3607x; 1.1691x over previous
#include <cuda_runtime.h>
#include <cuda_bf16.h>
#include <cstdint>

// Problem constants
#define Bq    16
#define Sq    2048
#define Dq    1024
#define Hq    16
#define CLIPq 8
#define NCq   256
#define DKq   64
#define NTOK  (Bq*Sq)                 // 32768 tokens
#define NELEM ((size_t)NTOK*Dq)       // 33554432 floats per (B,S,D) buffer

// Scratch pool (fp32 units):
//  0N..3N : bQ,bK,bV (fp32)
//  3N     : aHi/aLo (bf16 pair, = 1N fp32)
//  4N     : sHi/sLo
//  5N     : tHi/tLo
//  6N     : xHi/xLo
//  7N     : weight hi/lo pools (10M bf16 each = 40MB)
__device__ float g_buf[8ull*33554432ull];

__device__ __forceinline__ uint32_t smem_u32(const void* p) {
    uint32_t a;
    asm("{ .reg .u64 t; cvta.to.shared.u64 t, %1; cvt.u32.u64 %0, t; }"
        : "=r"(a) : "l"(p));
    return a;
}

__device__ __forceinline__ void ldsm4(uint32_t* r, uint32_t a) {
    asm volatile("ldmatrix.sync.aligned.m8n8.x4.shared.b16 {%0,%1,%2,%3}, [%4];"
        : "=r"(r[0]), "=r"(r[1]), "=r"(r[2]), "=r"(r[3]) : "r"(a));
}

__device__ __forceinline__ void mma_bf16(float* c,
    const uint32_t* a, uint32_t b0, uint32_t b1) {
    asm volatile("mma.sync.aligned.m16n8k16.row.col.f32.bf16.bf16.f32 "
        "{%0,%1,%2,%3}, {%4,%5,%6,%7}, {%8,%9}, {%0,%1,%2,%3};"
        : "+f"(c[0]), "+f"(c[1]), "+f"(c[2]), "+f"(c[3])
        : "r"(a[0]), "r"(a[1]), "r"(a[2]), "r"(a[3]), "r"(b0), "r"(b1));
}

__device__ __forceinline__ void cp16(uint32_t s, const void* g) {
    asm volatile("cp.async.cg.shared.global [%0], [%1], 16;" :: "r"(s), "l"(g));
}

__device__ __forceinline__ void split2(float x, float y,
    __nv_bfloat16* hi, __nv_bfloat16* lo) {
    __nv_bfloat16 hx = __float2bfloat16_rn(x);
    __nv_bfloat16 hy = __float2bfloat16_rn(y);
    __nv_bfloat16 lx = __float2bfloat16_rn(x - __bfloat162float(hx));
    __nv_bfloat16 ly = __float2bfloat16_rn(y - __bfloat162float(hy));
    ushort2 h2 = make_ushort2(__bfloat16_as_ushort(hx), __bfloat16_as_ushort(hy));
    ushort2 l2 = make_ushort2(__bfloat16_as_ushort(lx), __bfloat16_as_ushort(ly));
    *(ushort2*)hi = h2;
    *(ushort2*)lo = l2;
}

__device__ __forceinline__ void split4(const float* v,
    __nv_bfloat16* hi, __nv_bfloat16* lo) {
    ushort4 h4, l4;
    unsigned short* ph = &h4.x;
    unsigned short* pl = &l4.x;
    #pragma unroll
    for (int k = 0; k < 4; k++) {
        __nv_bfloat16 h = __float2bfloat16_rn(v[k]);
        __nv_bfloat16 l = __float2bfloat16_rn(v[k] - __bfloat162float(h));
        ph[k] = __bfloat16_as_ushort(h);
        pl[k] = __bfloat16_as_ushort(l);
    }
    *(ushort4*)hi = h4;
    *(ushort4*)lo = l4;
}

// ============================================================================
// bf16 3-pass GEMM via mma.sync: C[M,N] = (Ahi+Alo)[M,K] @ (Bhi+Blo)^T[N,K]
// (dropping Alo*Blo), fp32 register accumulation.
// Tile 128x128, BK=32, double-buffered cp.async, 256 threads (8 warps, 2x4),
// warp tile 64x32, 2 CTAs/SM. Sequential hi/lo passes keep <=32 operand regs.
// Epilogue: fp32 (optional beta accumulate) OR bf16 hi/lo split output.
// ============================================================================
#define TCSTRIDE 80                       // bytes per 32-elem bf16 row (+pad)
#define TCTILE   (128 * TCSTRIDE)         // 10240 B per operand tile
#define TCSTAGE  (4 * TCTILE)             // Ah, Al, Bh, Bl
#define TC_SMEM  (2 * TCSTAGE)            // 81920 B
#define NIT      (Dq / 32)                // 32 K-iterations

__global__ void __launch_bounds__(256, 2) tcgemm_kernel(
    const __nv_bfloat16* __restrict__ Ahi, const __nv_bfloat16* __restrict__ Alo,
    const __nv_bfloat16* __restrict__ Bhi, const __nv_bfloat16* __restrict__ Blo,
    const float* __restrict__ bias, float* __restrict__ C,
    __nv_bfloat16* __restrict__ Chi, __nv_bfloat16* __restrict__ Clo, int beta)
{
    extern __shared__ char smem[];
    const uint32_t sb = smem_u32(smem);
    const int tid  = threadIdx.x;
    const int lane = tid & 31;
    const int wid  = tid >> 5;
    const int wm = (wid >> 2) * 64;       // warp m offset in tile
    const int wn = (wid & 3) * 32;        // warp n offset in tile
    const int bm = blockIdx.y * 128;
    const int bn = blockIdx.x * 128;
    const int K  = Dq;

    const __nv_bfloat16* gptr[4] = {
        Ahi + (size_t)bm * K, Alo + (size_t)bm * K,
        Bhi + (size_t)bn * K, Blo + (size_t)bn * K };

    float acc[4][4][4];
    #pragma unroll
    for (int i = 0; i < 4; i++)
        #pragma unroll
        for (int j = 0; j < 4; j++)
            #pragma unroll
            for (int k = 0; k < 4; k++) acc[i][j][k] = 0.f;

    // ldmatrix per-lane address components
    const int rowA = (lane & 7) + ((lane >> 3) & 1) * 8;  // 0..15
    const int kbA  = (lane >> 4) * 16;                    // 0 or 16 bytes
    const int rowB = (lane & 7) + (lane >> 4) * 8;        // 0..15
    const int kbB  = ((lane >> 3) & 1) * 16;

    // async fill of one stage (BK=32): 4 tiles x 512 16B-chunks
    auto fill = [&](int it, int buf) {
        uint32_t sst = sb + buf * TCSTAGE;
        int k0 = it * 32;
        #pragma unroll
        for (int j = 0; j < 8; j++) {
            int t   = j >> 1;
            int rem = tid + (j & 1) * 256;       // 0..511
            int r   = rem >> 2, c = rem & 3;
            const void* g = gptr[t] + (size_t)r * K + k0 + c * 8;
            cp16(sst + t * TCTILE + r * TCSTRIDE + c * 16, g);
        }
        asm volatile("cp.async.commit_group;" ::: "memory");
    };

    fill(0, 0);

    for (int it = 0; it < NIT; it++) {
        if (it + 1 < NIT) {
            fill(it + 1, (it + 1) & 1);
            asm volatile("cp.async.wait_group 1;" ::: "memory");
        } else {
            asm volatile("cp.async.wait_group 0;" ::: "memory");
        }
        __syncthreads();

        uint32_t sst = sb + (it & 1) * TCSTAGE;
        uint32_t aHiB = sst + 0 * TCTILE + (wm + rowA) * TCSTRIDE + kbA;
        uint32_t aLoB = sst + 1 * TCTILE + (wm + rowA) * TCSTRIDE + kbA;
        uint32_t bHiB = sst + 2 * TCTILE + (wn + rowB) * TCSTRIDE + kbB;
        uint32_t bLoB = sst + 3 * TCTILE + (wn + rowB) * TCSTRIDE + kbB;

        #pragma unroll
        for (int ks = 0; ks < 2; ks++) {
            uint32_t a[4][4], bh[2][4], bl[2][4];
            // Pass 1: Ahi x Bhi
            #pragma unroll
            for (int mt = 0; mt < 4; mt++)
                ldsm4(a[mt], aHiB + mt * 16 * TCSTRIDE + ks * 32);
            #pragma unroll
            for (int p = 0; p < 2; p++)
                ldsm4(bh[p], bHiB + p * 16 * TCSTRIDE + ks * 32);
            #pragma unroll
            for (int mt = 0; mt < 4; mt++)
                #pragma unroll
                for (int nt = 0; nt < 4; nt++)
                    mma_bf16(acc[mt][nt], a[mt], bh[nt >> 1][(nt & 1) * 2],
                             bh[nt >> 1][(nt & 1) * 2 + 1]);
            // Pass 2: Ahi x Blo
            #pragma unroll
            for (int p = 0; p < 2; p++)
                ldsm4(bl[p], bLoB + p * 16 * TCSTRIDE + ks * 32);
            #pragma unroll
            for (int mt = 0; mt < 4; mt++)
                #pragma unroll
                for (int nt = 0; nt < 4; nt++)
                    mma_bf16(acc[mt][nt], a[mt], bl[nt >> 1][(nt & 1) * 2],
                             bl[nt >> 1][(nt & 1) * 2 + 1]);
            // Pass 3: Alo x Bhi (overwrite a with Alo)
            #pragma unroll
            for (int mt = 0; mt < 4; mt++)
                ldsm4(a[mt], aLoB + mt * 16 * TCSTRIDE + ks * 32);
            #pragma unroll
            for (int mt = 0; mt < 4; mt++)
                #pragma unroll
                for (int nt = 0; nt < 4; nt++)
                    mma_bf16(acc[mt][nt], a[mt], bh[nt >> 1][(nt & 1) * 2],
                             bh[nt >> 1][(nt & 1) * 2 + 1]);
        }
        __syncthreads();
    }

    // Epilogue
    #pragma unroll
    for (int mt = 0; mt < 4; mt++) {
        #pragma unroll
        for (int nt = 0; nt < 4; nt++) {
            int r0 = bm + wm + mt * 16 + (lane >> 2);
            int c0 = bn + wn + nt * 8 + (lane & 3) * 2;
            #pragma unroll
            for (int hrow = 0; hrow < 2; hrow++) {
                float vx = acc[mt][nt][hrow * 2];
                float vy = acc[mt][nt][hrow * 2 + 1];
                if (bias) {
                    vx += __ldg(&bias[c0]);
                    vy += __ldg(&bias[c0 + 1]);
                }
                size_t off = (size_t)(r0 + hrow * 8) * Dq + c0;
                if (Chi) {
                    split2(vx, vy, Chi + off, Clo + off);
                } else {
                    float* cp = C + off;
                    if (beta) {
                        float2 o = *(float2*)cp;
                        vx += o.x; vy += o.y;
                    }
                    *(float2*)cp = make_float2(vx, vy);
                }
            }
        }
    }
}

// ============================================================================
// fp32 -> bf16 hi/lo split (elementwise) — only used for x
// ============================================================================
__global__ void __launch_bounds__(256) split_kernel(
    const float* __restrict__ in, __nv_bfloat16* __restrict__ hi,
    __nv_bfloat16* __restrict__ lo, int n4)
{
    int i = blockIdx.x * 256 + threadIdx.x;
    if (i >= n4) return;
    float4 v = ((const float4*)in)[i];
    float f[4] = {v.x, v.y, v.z, v.w};
    split4(f, hi + (size_t)i * 4, lo + (size_t)i * 4);
}

// ============================================================================
// Weight transpose + split: W[1024 x 1024] row-major -> out[n][k] = W[k][n]
// ============================================================================
__global__ void __launch_bounds__(256) transpose_split_kernel(
    const float* __restrict__ W, __nv_bfloat16* __restrict__ hi,
    __nv_bfloat16* __restrict__ lo)
{
    __shared__ float t[32][33];
    int bx = blockIdx.x * 32, by = blockIdx.y * 32;
    int tx = threadIdx.x & 31, ty = threadIdx.x >> 5;   // 32 x 8
    #pragma unroll
    for (int j = 0; j < 32; j += 8)
        t[ty + j][tx] = W[(size_t)(by + ty + j) * 1024 + bx + tx];
    __syncthreads();
    #pragma unroll
    for (int j = 0; j < 32; j += 8) {
        float v = t[tx][ty + j];
        __nv_bfloat16 h = __float2bfloat16_rn(v);
        __nv_bfloat16 l = __float2bfloat16_rn(v - __bfloat162float(h));
        size_t o = (size_t)(bx + ty + j) * 1024 + by + tx;
        hi[o] = h; lo[o] = l;
    }
}

// ---------------------------------------------------------------------------
// Spatial attention: writes bf16 hi/lo directly (feeds O-projection GEMM)
// ---------------------------------------------------------------------------
__global__ __launch_bounds__(64) void spatial_attn_kernel(
    const float* __restrict__ Q, const float* __restrict__ K,
    const float* __restrict__ V, const int* __restrict__ mask,
    __nv_bfloat16* __restrict__ Ohi, __nv_bfloat16* __restrict__ Olo)
{
    __shared__ float sK[8][512];
    __shared__ float sV[8][512];
    int blk  = blockIdx.x;
    int half = blk & 1;
    int c    = (blk >> 1) & (NCq - 1);
    int b    = blk >> 9;
    size_t base = ((size_t)b * Sq + (size_t)c * CLIPq) * Dq;

    for (int idx = threadIdx.x; idx < 8 * 512 / 4; idx += 64) {
        int r = idx >> 7, c4 = idx & 127;
        size_t g = base + (size_t)r * Dq + half * 512 + c4 * 4;
        *(float4*)&sK[r][c4*4] = *(const float4*)&K[g];
        *(float4*)&sV[r][c4*4] = *(const float4*)&V[g];
    }
    __syncthreads();

    int hp = threadIdx.x >> 3;
    int i  = threadIdx.x & 7;
    int h  = half * 8 + hp;

    float q[64];
    const float* qg = &Q[base + (size_t)i * Dq + h * DKq];
    #pragma unroll
    for (int d = 0; d < 64; d += 4) {
        float4 t = *(const float4*)&qg[d];
        q[d] = t.x; q[d+1] = t.y; q[d+2] = t.z; q[d+3] = t.w;
    }

    float e[8]; float l = 0.f;
    #pragma unroll
    for (int j = 0; j < 8; j++) {
        const float* kr = &sK[j][hp * DKq];
        float s0 = 0.f, s1 = 0.f, s2 = 0.f, s3 = 0.f;
        #pragma unroll
        for (int d = 0; d < 64; d += 4) {
            s0 += q[d]   * kr[d];   s1 += q[d+1] * kr[d+1];
            s2 += q[d+2] * kr[d+2]; s3 += q[d+3] * kr[d+3];
        }
        float s = (s0 + s1 + s2 + s3) * 0.125f;
        float ee = mask[b * Sq + c * CLIPq + j] ? __expf(s) : 0.f;
        e[j] = ee; l += ee;
    }
    float inv = 1.f / l;

    float out[64];
    #pragma unroll
    for (int d = 0; d < 64; d++) out[d] = 0.f;
    #pragma unroll
    for (int j = 0; j < 8; j++) {
        const float* vr = &sV[j][hp * DKq];
        float ej = e[j];
        #pragma unroll
        for (int d = 0; d < 64; d++) out[d] += ej * vr[d];
    }

    size_t ob = base + (size_t)i * Dq + h * DKq;
    #pragma unroll
    for (int d = 0; d < 64; d += 4) {
        float v[4] = {out[d]*inv, out[d+1]*inv, out[d+2]*inv, out[d+3]*inv};
        split4(v, Ohi + ob + d, Olo + ob + d);
    }
}

// ---------------------------------------------------------------------------
// Temporal attention: writes bf16 hi/lo directly
// ---------------------------------------------------------------------------
__global__ __launch_bounds__(256) void temporal_attn_kernel(
    const float* __restrict__ Q, const float* __restrict__ K,
    const float* __restrict__ V, const int* __restrict__ mask,
    __nv_bfloat16* __restrict__ Ohi, __nv_bfloat16* __restrict__ Olo)
{
    __shared__ float sK[64][64];
    __shared__ float sV[64][64];
    __shared__ float sM[256];
    int blk = blockIdx.x;
    int h = blk & 15;
    int p = (blk >> 4) & 7;
    int b = blk >> 7;
    int cq = threadIdx.x;

    sM[cq] = mask[b * Sq + cq * CLIPq + p] ? 1.f : 0.f;

    float q[64];
    size_t qbase = ((size_t)b * Sq + (size_t)cq * CLIPq + p) * Dq + h * DKq;
    #pragma unroll
    for (int d = 0; d < 64; d += 4) {
        float4 t = *(const float4*)&Q[qbase + d];
        q[d] = t.x; q[d+1] = t.y; q[d+2] = t.z; q[d+3] = t.w;
    }

    float acc[64];
    #pragma unroll
    for (int d = 0; d < 64; d++) acc[d] = 0.f;
    float l = 0.f;

    for (int t0 = 0; t0 < NCq; t0 += 64) {
        for (int idx = threadIdx.x; idx < 1024; idx += 256) {
            int r = idx >> 4, c4 = idx & 15;
            size_t gb = ((size_t)b * Sq + (size_t)(t0 + r) * CLIPq + p) * Dq
                        + h * DKq + c4 * 4;
            *(float4*)&sK[r][c4*4] = *(const float4*)&K[gb];
            *(float4*)&sV[r][c4*4] = *(const float4*)&V[gb];
        }
        __syncthreads();
        #pragma unroll 4
        for (int j = 0; j < 64; j++) {
            float s0 = 0.f, s1 = 0.f, s2 = 0.f, s3 = 0.f;
            #pragma unroll
            for (int d = 0; d < 64; d += 4) {
                s0 += q[d]   * sK[j][d];   s1 += q[d+1] * sK[j][d+1];
                s2 += q[d+2] * sK[j][d+2]; s3 += q[d+3] * sK[j][d+3];
            }
            float e = __expf((s0 + s1 + s2 + s3) * 0.125f) * sM[t0 + j];
            l += e;
            #pragma unroll
            for (int d = 0; d < 64; d++) acc[d] += e * sV[j][d];
        }
        __syncthreads();
    }

    float inv = 1.f / l;
    #pragma unroll
    for (int d = 0; d < 64; d += 4) {
        float v[4] = {acc[d]*inv, acc[d+1]*inv, acc[d+2]*inv, acc[d+3]*inv};
        split4(v, Ohi + qbase + d, Olo + qbase + d);
    }
}

// ---------------------------------------------------------------------------
// Launch
// ---------------------------------------------------------------------------
extern "C" void kernel_launch(void* const* d_in, const int* in_sizes, int n_in,
                              void* d_out, int out_size)
{
    const float* x      = (const float*)d_in[0];
    const int*   mask   = (const int*)  d_in[1];
    const float* wsrc[10] = {
        (const float*)d_in[2],  // sa_q_w
        (const float*)d_in[4],  // sa_k_w
        (const float*)d_in[6],  // sa_v_w
        (const float*)d_in[8],  // sa_o_w
        (const float*)d_in[10], // ta_q_w
        (const float*)d_in[12], // ta_k_w
        (const float*)d_in[14], // ta_v_w
        (const float*)d_in[16], // ta_o_w
        (const float*)d_in[18],                          // fuse_w rows 0..1023
        (const float*)d_in[18] + (size_t)1024 * 1024     // fuse_w rows 1024..2047
    };
    const float* sa_q_b = (const float*)d_in[3];
    const float* sa_k_b = (const float*)d_in[5];
    const float* sa_v_b = (const float*)d_in[7];
    const float* sa_o_b = (const float*)d_in[9];
    const float* ta_q_b = (const float*)d_in[11];
    const float* ta_k_b = (const float*)d_in[13];
    const float* ta_v_b = (const float*)d_in[15];
    const float* ta_o_b = (const float*)d_in[17];
    const float* fuse_b = (const float*)d_in[19];
    float* out = (float*)d_out;

    float* base = nullptr;
    cudaGetSymbolAddress((void**)&base, g_buf);
    float* bQ = base;
    float* bK = base + NELEM;
    float* bV = base + 2*NELEM;
    __nv_bfloat16* aHi = (__nv_bfloat16*)(base + 3*NELEM);
    __nv_bfloat16* aLo = aHi + NELEM;
    __nv_bfloat16* sHi = (__nv_bfloat16*)(base + 4*NELEM);
    __nv_bfloat16* sLo = sHi + NELEM;
    __nv_bfloat16* tHi = (__nv_bfloat16*)(base + 5*NELEM);
    __nv_bfloat16* tLo = tHi + NELEM;
    __nv_bfloat16* xHi = (__nv_bfloat16*)(base + 6*NELEM);
    __nv_bfloat16* xLo = xHi + NELEM;
    __nv_bfloat16* wHi = (__nv_bfloat16*)(base + 7*NELEM);
    __nv_bfloat16* wLo = wHi + (size_t)10 * 1024 * 1024;

    cudaFuncSetAttribute(tcgemm_kernel,
        cudaFuncAttributeMaxDynamicSharedMemorySize, TC_SMEM);

    const int n4 = (int)(NELEM / 4);
    const int splitBlocks = (n4 + 255) / 256;
    dim3 tgrid(32, 32), tblk(256);
    dim3 ggrid(Dq / 128, NTOK / 128);   // (8, 256)

    // Prep: split x, transpose+split all weights
    split_kernel<<<splitBlocks, 256>>>(x, xHi, xLo, n4);
    for (int i = 0; i < 10; i++)
        transpose_split_kernel<<<tgrid, tblk>>>(wsrc[i],
            wHi + (size_t)i * 1024 * 1024, wLo + (size_t)i * 1024 * 1024);

    #define WT(i) (wHi + (size_t)(i)*1024*1024), (wLo + (size_t)(i)*1024*1024)
    #define NOHL  (__nv_bfloat16*)nullptr, (__nv_bfloat16*)nullptr

    // Spatial branch
    tcgemm_kernel<<<ggrid, 256, TC_SMEM>>>(xHi, xLo, WT(0), sa_q_b, bQ, NOHL, 0);
    tcgemm_kernel<<<ggrid, 256, TC_SMEM>>>(xHi, xLo, WT(1), sa_k_b, bK, NOHL, 0);
    tcgemm_kernel<<<ggrid, 256, TC_SMEM>>>(xHi, xLo, WT(2), sa_v_b, bV, NOHL, 0);
    spatial_attn_kernel<<<Bq*NCq*2, 64>>>(bQ, bK, bV, mask, aHi, aLo);
    tcgemm_kernel<<<ggrid, 256, TC_SMEM>>>(aHi, aLo, WT(3), sa_o_b, nullptr, sHi, sLo, 0);

    // Temporal branch
    tcgemm_kernel<<<ggrid, 256, TC_SMEM>>>(xHi, xLo, WT(4), ta_q_b, bQ, NOHL, 0);
    tcgemm_kernel<<<ggrid, 256, TC_SMEM>>>(xHi, xLo, WT(5), ta_k_b, bK, NOHL, 0);
    tcgemm_kernel<<<ggrid, 256, TC_SMEM>>>(xHi, xLo, WT(6), ta_v_b, bV, NOHL, 0);
    temporal_attn_kernel<<<Bq*CLIPq*Hq, 256>>>(bQ, bK, bV, mask, aHi, aLo);
    tcgemm_kernel<<<ggrid, 256, TC_SMEM>>>(aHi, aLo, WT(7), ta_o_b, nullptr, tHi, tLo, 0);

    // Fuse: out = bS @ fuse_w[0:1024] + fuse_b + bT @ fuse_w[1024:2048]
    tcgemm_kernel<<<ggrid, 256, TC_SMEM>>>(sHi, sLo, WT(8), fuse_b, out, NOHL, 0);
    tcgemm_kernel<<<ggrid, 256, TC_SMEM>>>(tHi, tLo, WT(9), nullptr, out, NOHL, 1);
}

// round 6
// speedup vs baseline: 4.0909x; 1.7329x over previous
#include <cuda_runtime.h>
#include <cuda_fp16.h>
#include <cstdint>

// Problem constants
#define Bq    16
#define Sq    2048
#define Dq    1024
#define Hq    16
#define CLIPq 8
#define NCq   256
#define DKq   64
#define NTOK  (Bq*Sq)                 // 32768 tokens
#define NELEM ((size_t)NTOK*Dq)       // 33554432 floats per (B,S,D) buffer

// Scratch pool (fp32 units):
//  0N..3N : bQ,bK,bV (fp32)
//  3N..4N : xH, aH   (fp16, NELEM halves each)
//  4N..5N : sH, tH   (fp16)
//  5N..   : weight fp16 pool (10 x 1M halves = 20MB)
__device__ float g_buf[6ull*33554432ull];

__device__ __forceinline__ uint32_t smem_u32(const void* p) {
    uint32_t a;
    asm("{ .reg .u64 t; cvta.to.shared.u64 t, %1; cvt.u32.u64 %0, t; }"
        : "=r"(a) : "l"(p));
    return a;
}

__device__ __forceinline__ void ldsm4(uint32_t* r, uint32_t a) {
    asm volatile("ldmatrix.sync.aligned.m8n8.x4.shared.b16 {%0,%1,%2,%3}, [%4];"
        : "=r"(r[0]), "=r"(r[1]), "=r"(r[2]), "=r"(r[3]) : "r"(a));
}

__device__ __forceinline__ void mma_f16(float* c,
    const uint32_t* a, uint32_t b0, uint32_t b1) {
    asm volatile("mma.sync.aligned.m16n8k16.row.col.f32.f16.f16.f32 "
        "{%0,%1,%2,%3}, {%4,%5,%6,%7}, {%8,%9}, {%0,%1,%2,%3};"
        : "+f"(c[0]), "+f"(c[1]), "+f"(c[2]), "+f"(c[3])
        : "r"(a[0]), "r"(a[1]), "r"(a[2]), "r"(a[3]), "r"(b0), "r"(b1));
}

__device__ __forceinline__ void cp16(uint32_t s, const void* g) {
    asm volatile("cp.async.cg.shared.global [%0], [%1], 16;" :: "r"(s), "l"(g));
}

// ============================================================================
// fp16 single-pass GEMM via mma.sync: C[M,N] = A[M,K] @ B^T[N,K] (+bias/+beta)
// fp32 register accumulation. Tile 128x128, BK=32, double-buffered cp.async,
// 256 threads (8 warps, 2x4), warp tile 64x32, 2 CTAs/SM.
// Epilogue: fp32 out (optional beta accumulate) OR fp16 out.
// ============================================================================
#define TCSTRIDE 80                       // bytes per 32-elem fp16 row (+pad)
#define TCTILE   (128 * TCSTRIDE)         // 10240 B per operand tile
#define TCSTAGE  (2 * TCTILE)             // A, B
#define TC_SMEM  (2 * TCSTAGE)            // 40960 B
#define NIT      (Dq / 32)                // 32 K-iterations

__global__ void __launch_bounds__(256, 2) tcgemm_kernel(
    const __half* __restrict__ A, const __half* __restrict__ B,
    const float* __restrict__ bias, float* __restrict__ C,
    __half* __restrict__ Ch, int beta)
{
    extern __shared__ char smem[];
    const uint32_t sb = smem_u32(smem);
    const int tid  = threadIdx.x;
    const int lane = tid & 31;
    const int wid  = tid >> 5;
    const int wm = (wid >> 2) * 64;       // warp m offset in tile
    const int wn = (wid & 3) * 32;        // warp n offset in tile
    const int bm = blockIdx.y * 128;
    const int bn = blockIdx.x * 128;
    const int K  = Dq;

    const __half* gptr[2] = { A + (size_t)bm * K, B + (size_t)bn * K };

    float acc[4][4][4];
    #pragma unroll
    for (int i = 0; i < 4; i++)
        #pragma unroll
        for (int j = 0; j < 4; j++)
            #pragma unroll
            for (int k = 0; k < 4; k++) acc[i][j][k] = 0.f;

    // ldmatrix per-lane address components
    const int rowA = (lane & 7) + ((lane >> 3) & 1) * 8;  // 0..15
    const int kbA  = (lane >> 4) * 16;                    // 0 or 16 bytes
    const int rowB = (lane & 7) + (lane >> 4) * 8;        // 0..15
    const int kbB  = ((lane >> 3) & 1) * 16;

    // async fill of one stage (BK=32): 2 tiles x 512 16B-chunks
    auto fill = [&](int it, int buf) {
        uint32_t sst = sb + buf * TCSTAGE;
        int k0 = it * 32;
        #pragma unroll
        for (int j = 0; j < 4; j++) {
            int t   = j >> 1;
            int rem = tid + (j & 1) * 256;       // 0..511
            int r   = rem >> 2, c = rem & 3;
            const void* g = gptr[t] + (size_t)r * K + k0 + c * 8;
            cp16(sst + t * TCTILE + r * TCSTRIDE + c * 16, g);
        }
        asm volatile("cp.async.commit_group;" ::: "memory");
    };

    fill(0, 0);

    for (int it = 0; it < NIT; it++) {
        if (it + 1 < NIT) {
            fill(it + 1, (it + 1) & 1);
            asm volatile("cp.async.wait_group 1;" ::: "memory");
        } else {
            asm volatile("cp.async.wait_group 0;" ::: "memory");
        }
        __syncthreads();

        uint32_t sst = sb + (it & 1) * TCSTAGE;
        uint32_t aB = sst + 0 * TCTILE + (wm + rowA) * TCSTRIDE + kbA;
        uint32_t bB = sst + 1 * TCTILE + (wn + rowB) * TCSTRIDE + kbB;

        #pragma unroll
        for (int ks = 0; ks < 2; ks++) {
            uint32_t a[4][4], b[2][4];
            #pragma unroll
            for (int mt = 0; mt < 4; mt++)
                ldsm4(a[mt], aB + mt * 16 * TCSTRIDE + ks * 32);
            #pragma unroll
            for (int p = 0; p < 2; p++)
                ldsm4(b[p], bB + p * 16 * TCSTRIDE + ks * 32);
            #pragma unroll
            for (int mt = 0; mt < 4; mt++)
                #pragma unroll
                for (int nt = 0; nt < 4; nt++)
                    mma_f16(acc[mt][nt], a[mt], b[nt >> 1][(nt & 1) * 2],
                            b[nt >> 1][(nt & 1) * 2 + 1]);
        }
        __syncthreads();
    }

    // Epilogue
    #pragma unroll
    for (int mt = 0; mt < 4; mt++) {
        #pragma unroll
        for (int nt = 0; nt < 4; nt++) {
            int r0 = bm + wm + mt * 16 + (lane >> 2);
            int c0 = bn + wn + nt * 8 + (lane & 3) * 2;
            #pragma unroll
            for (int hrow = 0; hrow < 2; hrow++) {
                float vx = acc[mt][nt][hrow * 2];
                float vy = acc[mt][nt][hrow * 2 + 1];
                if (bias) {
                    vx += __ldg(&bias[c0]);
                    vy += __ldg(&bias[c0 + 1]);
                }
                size_t off = (size_t)(r0 + hrow * 8) * Dq + c0;
                if (Ch) {
                    *(__half2*)(Ch + off) = __floats2half2_rn(vx, vy);
                } else {
                    float* cp = C + off;
                    if (beta) {
                        float2 o = *(float2*)cp;
                        vx += o.x; vy += o.y;
                    }
                    *(float2*)cp = make_float2(vx, vy);
                }
            }
        }
    }
}

// ============================================================================
// fp32 -> fp16 convert (elementwise) — only used for x
// ============================================================================
__global__ void __launch_bounds__(256) conv_kernel(
    const float* __restrict__ in, __half* __restrict__ out, int n4)
{
    int i = blockIdx.x * 256 + threadIdx.x;
    if (i >= n4) return;
    float4 v = ((const float4*)in)[i];
    ((__half2*)out)[i * 2]     = __floats2half2_rn(v.x, v.y);
    ((__half2*)out)[i * 2 + 1] = __floats2half2_rn(v.z, v.w);
}

// ============================================================================
// Weight transpose + fp16: W[1024 x 1024] row-major -> out[n][k] = h(W[k][n])
// ============================================================================
__global__ void __launch_bounds__(256) transpose_h_kernel(
    const float* __restrict__ W, __half* __restrict__ out)
{
    __shared__ float t[32][33];
    int bx = blockIdx.x * 32, by = blockIdx.y * 32;
    int tx = threadIdx.x & 31, ty = threadIdx.x >> 5;   // 32 x 8
    #pragma unroll
    for (int j = 0; j < 32; j += 8)
        t[ty + j][tx] = W[(size_t)(by + ty + j) * 1024 + bx + tx];
    __syncthreads();
    #pragma unroll
    for (int j = 0; j < 32; j += 8) {
        size_t o = (size_t)(bx + ty + j) * 1024 + by + tx;
        out[o] = __float2half_rn(t[tx][ty + j]);
    }
}

// ---------------------------------------------------------------------------
// Spatial attention: fp32 in, fp16 out (feeds O-projection GEMM)
// ---------------------------------------------------------------------------
__global__ __launch_bounds__(64) void spatial_attn_kernel(
    const float* __restrict__ Q, const float* __restrict__ K,
    const float* __restrict__ V, const int* __restrict__ mask,
    __half* __restrict__ O)
{
    __shared__ float sK[8][512];
    __shared__ float sV[8][512];
    int blk  = blockIdx.x;
    int half = blk & 1;
    int c    = (blk >> 1) & (NCq - 1);
    int b    = blk >> 9;
    size_t base = ((size_t)b * Sq + (size_t)c * CLIPq) * Dq;

    for (int idx = threadIdx.x; idx < 8 * 512 / 4; idx += 64) {
        int r = idx >> 7, c4 = idx & 127;
        size_t g = base + (size_t)r * Dq + half * 512 + c4 * 4;
        *(float4*)&sK[r][c4*4] = *(const float4*)&K[g];
        *(float4*)&sV[r][c4*4] = *(const float4*)&V[g];
    }
    __syncthreads();

    int hp = threadIdx.x >> 3;
    int i  = threadIdx.x & 7;
    int h  = half * 8 + hp;

    float q[64];
    const float* qg = &Q[base + (size_t)i * Dq + h * DKq];
    #pragma unroll
    for (int d = 0; d < 64; d += 4) {
        float4 t = *(const float4*)&qg[d];
        q[d] = t.x; q[d+1] = t.y; q[d+2] = t.z; q[d+3] = t.w;
    }

    float e[8]; float l = 0.f;
    #pragma unroll
    for (int j = 0; j < 8; j++) {
        const float* kr = &sK[j][hp * DKq];
        float s0 = 0.f, s1 = 0.f, s2 = 0.f, s3 = 0.f;
        #pragma unroll
        for (int d = 0; d < 64; d += 4) {
            s0 += q[d]   * kr[d];   s1 += q[d+1] * kr[d+1];
            s2 += q[d+2] * kr[d+2]; s3 += q[d+3] * kr[d+3];
        }
        float s = (s0 + s1 + s2 + s3) * 0.125f;
        float ee = mask[b * Sq + c * CLIPq + j] ? __expf(s) : 0.f;
        e[j] = ee; l += ee;
    }
    float inv = 1.f / l;

    float out[64];
    #pragma unroll
    for (int d = 0; d < 64; d++) out[d] = 0.f;
    #pragma unroll
    for (int j = 0; j < 8; j++) {
        const float* vr = &sV[j][hp * DKq];
        float ej = e[j];
        #pragma unroll
        for (int d = 0; d < 64; d++) out[d] += ej * vr[d];
    }

    size_t ob = base + (size_t)i * Dq + h * DKq;
    #pragma unroll
    for (int d = 0; d < 64; d += 2)
        *(__half2*)(O + ob + d) = __floats2half2_rn(out[d]*inv, out[d+1]*inv);
}

// ---------------------------------------------------------------------------
// Temporal attention: fp32 in, fp16 out
// ---------------------------------------------------------------------------
__global__ __launch_bounds__(256) void temporal_attn_kernel(
    const float* __restrict__ Q, const float* __restrict__ K,
    const float* __restrict__ V, const int* __restrict__ mask,
    __half* __restrict__ O)
{
    __shared__ float sK[64][64];
    __shared__ float sV[64][64];
    __shared__ float sM[256];
    int blk = blockIdx.x;
    int h = blk & 15;
    int p = (blk >> 4) & 7;
    int b = blk >> 7;
    int cq = threadIdx.x;

    sM[cq] = mask[b * Sq + cq * CLIPq + p] ? 1.f : 0.f;

    float q[64];
    size_t qbase = ((size_t)b * Sq + (size_t)cq * CLIPq + p) * Dq + h * DKq;
    #pragma unroll
    for (int d = 0; d < 64; d += 4) {
        float4 t = *(const float4*)&Q[qbase + d];
        q[d] = t.x; q[d+1] = t.y; q[d+2] = t.z; q[d+3] = t.w;
    }

    float acc[64];
    #pragma unroll
    for (int d = 0; d < 64; d++) acc[d] = 0.f;
    float l = 0.f;

    for (int t0 = 0; t0 < NCq; t0 += 64) {
        for (int idx = threadIdx.x; idx < 1024; idx += 256) {
            int r = idx >> 4, c4 = idx & 15;
            size_t gb = ((size_t)b * Sq + (size_t)(t0 + r) * CLIPq + p) * Dq
                        + h * DKq + c4 * 4;
            *(float4*)&sK[r][c4*4] = *(const float4*)&K[gb];
            *(float4*)&sV[r][c4*4] = *(const float4*)&V[gb];
        }
        __syncthreads();
        #pragma unroll 4
        for (int j = 0; j < 64; j++) {
            float s0 = 0.f, s1 = 0.f, s2 = 0.f, s3 = 0.f;
            #pragma unroll
            for (int d = 0; d < 64; d += 4) {
                s0 += q[d]   * sK[j][d];   s1 += q[d+1] * sK[j][d+1];
                s2 += q[d+2] * sK[j][d+2]; s3 += q[d+3] * sK[j][d+3];
            }
            float e = __expf((s0 + s1 + s2 + s3) * 0.125f) * sM[t0 + j];
            l += e;
            #pragma unroll
            for (int d = 0; d < 64; d++) acc[d] += e * sV[j][d];
        }
        __syncthreads();
    }

    float inv = 1.f / l;
    #pragma unroll
    for (int d = 0; d < 64; d += 2)
        *(__half2*)(O + qbase + d) = __floats2half2_rn(acc[d]*inv, acc[d+1]*inv);
}

// ---------------------------------------------------------------------------
// Launch
// ---------------------------------------------------------------------------
extern "C" void kernel_launch(void* const* d_in, const int* in_sizes, int n_in,
                              void* d_out, int out_size)
{
    const float* x      = (const float*)d_in[0];
    const int*   mask   = (const int*)  d_in[1];
    const float* wsrc[10] = {
        (const float*)d_in[2],  // sa_q_w
        (const float*)d_in[4],  // sa_k_w
        (const float*)d_in[6],  // sa_v_w
        (const float*)d_in[8],  // sa_o_w
        (const float*)d_in[10], // ta_q_w
        (const float*)d_in[12], // ta_k_w
        (const float*)d_in[14], // ta_v_w
        (const float*)d_in[16], // ta_o_w
        (const float*)d_in[18],                          // fuse_w rows 0..1023
        (const float*)d_in[18] + (size_t)1024 * 1024     // fuse_w rows 1024..2047
    };
    const float* sa_q_b = (const float*)d_in[3];
    const float* sa_k_b = (const float*)d_in[5];
    const float* sa_v_b = (const float*)d_in[7];
    const float* sa_o_b = (const float*)d_in[9];
    const float* ta_q_b = (const float*)d_in[11];
    const float* ta_k_b = (const float*)d_in[13];
    const float* ta_v_b = (const float*)d_in[15];
    const float* ta_o_b = (const float*)d_in[17];
    const float* fuse_b = (const float*)d_in[19];
    float* out = (float*)d_out;

    float* base = nullptr;
    cudaGetSymbolAddress((void**)&base, g_buf);
    float* bQ = base;
    float* bK = base + NELEM;
    float* bV = base + 2*NELEM;
    __half* xH = (__half*)(base + 3*NELEM);
    __half* aH = xH + NELEM;
    __half* sH = (__half*)(base + 4*NELEM);
    __half* tH = sH + NELEM;
    __half* wH = (__half*)(base + 5*NELEM);

    cudaFuncSetAttribute(tcgemm_kernel,
        cudaFuncAttributeMaxDynamicSharedMemorySize, TC_SMEM);

    const int n4 = (int)(NELEM / 4);
    const int convBlocks = (n4 + 255) / 256;
    dim3 tgrid(32, 32), tblk(256);
    dim3 ggrid(Dq / 128, NTOK / 128);   // (8, 256)

    // Prep: convert x, transpose+convert all weights
    conv_kernel<<<convBlocks, 256>>>(x, xH, n4);
    for (int i = 0; i < 10; i++)
        transpose_h_kernel<<<tgrid, tblk>>>(wsrc[i], wH + (size_t)i * 1024 * 1024);

    #define WT(i) (wH + (size_t)(i)*1024*1024)
    #define NOH   (__half*)nullptr

    // Spatial branch
    tcgemm_kernel<<<ggrid, 256, TC_SMEM>>>(xH, WT(0), sa_q_b, bQ, NOH, 0);
    tcgemm_kernel<<<ggrid, 256, TC_SMEM>>>(xH, WT(1), sa_k_b, bK, NOH, 0);
    tcgemm_kernel<<<ggrid, 256, TC_SMEM>>>(xH, WT(2), sa_v_b, bV, NOH, 0);
    spatial_attn_kernel<<<Bq*NCq*2, 64>>>(bQ, bK, bV, mask, aH);
    tcgemm_kernel<<<ggrid, 256, TC_SMEM>>>(aH, WT(3), sa_o_b, nullptr, sH, 0);

    // Temporal branch
    tcgemm_kernel<<<ggrid, 256, TC_SMEM>>>(xH, WT(4), ta_q_b, bQ, NOH, 0);
    tcgemm_kernel<<<ggrid, 256, TC_SMEM>>>(xH, WT(5), ta_k_b, bK, NOH, 0);
    tcgemm_kernel<<<ggrid, 256, TC_SMEM>>>(xH, WT(6), ta_v_b, bV, NOH, 0);
    temporal_attn_kernel<<<Bq*CLIPq*Hq, 256>>>(bQ, bK, bV, mask, aH);
    tcgemm_kernel<<<ggrid, 256, TC_SMEM>>>(aH, WT(7), ta_o_b, nullptr, tH, 0);

    // Fuse: out = s @ fuse_w[0:1024] + fuse_b + t @ fuse_w[1024:2048]
    tcgemm_kernel<<<ggrid, 256, TC_SMEM>>>(sH, WT(8), fuse_b, out, NOH, 0);
    tcgemm_kernel<<<ggrid, 256, TC_SMEM>>>(tH, WT(9), nullptr, out, NOH, 1);
}

// round 9
// speedup vs baseline: 5.6013x; 1.3692x over previous
#include <cuda_runtime.h>
#include <cuda_fp16.h>
#include <cstdint>

// Problem constants
#define Bq    16
#define Sq    2048
#define Dq    1024
#define Hq    16
#define CLIPq 8
#define NCq   256
#define DKq   64
#define NTOK  (Bq*Sq)                 // 32768 tokens
#define NELEM ((size_t)NTOK*Dq)       // 33554432 elems per (B,S,D) buffer

// Scratch pool: all-fp16 activations.
//  halves: qH,kH,vH,aH,sH,tH,xH = 7*NELEM, wH = 10M  (~490MB total)
__device__ float g_buf[6ull*33554432ull];

__device__ __forceinline__ uint32_t smem_u32(const void* p) {
    uint32_t a;
    asm("{ .reg .u64 t; cvta.to.shared.u64 t, %1; cvt.u32.u64 %0, t; }"
        : "=r"(a) : "l"(p));
    return a;
}

__device__ __forceinline__ void ldsm4(uint32_t* r, uint32_t a) {
    asm volatile("ldmatrix.sync.aligned.m8n8.x4.shared.b16 {%0,%1,%2,%3}, [%4];"
        : "=r"(r[0]), "=r"(r[1]), "=r"(r[2]), "=r"(r[3]) : "r"(a));
}

__device__ __forceinline__ void mma_f16(float* c,
    const uint32_t* a, uint32_t b0, uint32_t b1) {
    asm volatile("mma.sync.aligned.m16n8k16.row.col.f32.f16.f16.f32 "
        "{%0,%1,%2,%3}, {%4,%5,%6,%7}, {%8,%9}, {%0,%1,%2,%3};"
        : "+f"(c[0]), "+f"(c[1]), "+f"(c[2]), "+f"(c[3])
        : "r"(a[0]), "r"(a[1]), "r"(a[2]), "r"(a[3]), "r"(b0), "r"(b1));
}

__device__ __forceinline__ void cp16(uint32_t s, const void* g) {
    asm volatile("cp.async.cg.shared.global [%0], [%1], 16;" :: "r"(s), "l"(g));
}

__device__ __forceinline__ uint32_t packh2(float x, float y) {
    __half2 h = __floats2half2_rn(x, y);
    return *(uint32_t*)&h;
}

// ============================================================================
// fp16 single-pass GEMM via mma.sync
// ============================================================================
#define TCSTRIDE 80
#define TCTILE   (128 * TCSTRIDE)
#define TCSTAGE  (2 * TCTILE)
#define TC_SMEM  (2 * TCSTAGE)            // 40960 B
#define NIT      (Dq / 32)

__global__ void __launch_bounds__(256, 2) tcgemm_kernel(
    const __half* __restrict__ A, const __half* __restrict__ B,
    const float* __restrict__ bias, float* __restrict__ C,
    __half* __restrict__ Ch, int beta)
{
    extern __shared__ char smem[];
    const uint32_t sb = smem_u32(smem);
    const int tid  = threadIdx.x;
    const int lane = tid & 31;
    const int wid  = tid >> 5;
    const int wm = (wid >> 2) * 64;
    const int wn = (wid & 3) * 32;
    const int bm = blockIdx.y * 128;
    const int bn = blockIdx.x * 128;
    const int K  = Dq;

    const __half* gptr[2] = { A + (size_t)bm * K, B + (size_t)bn * K };

    float acc[4][4][4];
    #pragma unroll
    for (int i = 0; i < 4; i++)
        #pragma unroll
        for (int j = 0; j < 4; j++)
            #pragma unroll
            for (int k = 0; k < 4; k++) acc[i][j][k] = 0.f;

    const int rowA = (lane & 7) + ((lane >> 3) & 1) * 8;
    const int kbA  = (lane >> 4) * 16;
    const int rowB = (lane & 7) + (lane >> 4) * 8;
    const int kbB  = ((lane >> 3) & 1) * 16;

    auto fill = [&](int it, int buf) {
        uint32_t sst = sb + buf * TCSTAGE;
        int k0 = it * 32;
        #pragma unroll
        for (int j = 0; j < 4; j++) {
            int t   = j >> 1;
            int rem = tid + (j & 1) * 256;
            int r   = rem >> 2, c = rem & 3;
            const void* g = gptr[t] + (size_t)r * K + k0 + c * 8;
            cp16(sst + t * TCTILE + r * TCSTRIDE + c * 16, g);
        }
        asm volatile("cp.async.commit_group;" ::: "memory");
    };

    fill(0, 0);

    for (int it = 0; it < NIT; it++) {
        if (it + 1 < NIT) {
            fill(it + 1, (it + 1) & 1);
            asm volatile("cp.async.wait_group 1;" ::: "memory");
        } else {
            asm volatile("cp.async.wait_group 0;" ::: "memory");
        }
        __syncthreads();

        uint32_t sst = sb + (it & 1) * TCSTAGE;
        uint32_t aB = sst + 0 * TCTILE + (wm + rowA) * TCSTRIDE + kbA;
        uint32_t bB = sst + 1 * TCTILE + (wn + rowB) * TCSTRIDE + kbB;

        #pragma unroll
        for (int ks = 0; ks < 2; ks++) {
            uint32_t a[4][4], b[2][4];
            #pragma unroll
            for (int mt = 0; mt < 4; mt++)
                ldsm4(a[mt], aB + mt * 16 * TCSTRIDE + ks * 32);
            #pragma unroll
            for (int p = 0; p < 2; p++)
                ldsm4(b[p], bB + p * 16 * TCSTRIDE + ks * 32);
            #pragma unroll
            for (int mt = 0; mt < 4; mt++)
                #pragma unroll
                for (int nt = 0; nt < 4; nt++)
                    mma_f16(acc[mt][nt], a[mt], b[nt >> 1][(nt & 1) * 2],
                            b[nt >> 1][(nt & 1) * 2 + 1]);
        }
        __syncthreads();
    }

    #pragma unroll
    for (int mt = 0; mt < 4; mt++) {
        #pragma unroll
        for (int nt = 0; nt < 4; nt++) {
            int r0 = bm + wm + mt * 16 + (lane >> 2);
            int c0 = bn + wn + nt * 8 + (lane & 3) * 2;
            #pragma unroll
            for (int hrow = 0; hrow < 2; hrow++) {
                float vx = acc[mt][nt][hrow * 2];
                float vy = acc[mt][nt][hrow * 2 + 1];
                if (bias) {
                    vx += __ldg(&bias[c0]);
                    vy += __ldg(&bias[c0 + 1]);
                }
                size_t off = (size_t)(r0 + hrow * 8) * Dq + c0;
                if (Ch) {
                    *(__half2*)(Ch + off) = __floats2half2_rn(vx, vy);
                } else {
                    float* cp = C + off;
                    if (beta) {
                        float2 o = *(float2*)cp;
                        vx += o.x; vy += o.y;
                    }
                    *(float2*)cp = make_float2(vx, vy);
                }
            }
        }
    }
}

// ============================================================================
// fp32 -> fp16 convert (x only)
// ============================================================================
__global__ void __launch_bounds__(256) conv_kernel(
    const float* __restrict__ in, __half* __restrict__ out, int n4)
{
    int i = blockIdx.x * 256 + threadIdx.x;
    if (i >= n4) return;
    float4 v = ((const float4*)in)[i];
    ((__half2*)out)[i * 2]     = __floats2half2_rn(v.x, v.y);
    ((__half2*)out)[i * 2 + 1] = __floats2half2_rn(v.z, v.w);
}

// ============================================================================
// Weight transpose + fp16
// ============================================================================
__global__ void __launch_bounds__(256) transpose_h_kernel(
    const float* __restrict__ W, __half* __restrict__ out)
{
    __shared__ float t[32][33];
    int bx = blockIdx.x * 32, by = blockIdx.y * 32;
    int tx = threadIdx.x & 31, ty = threadIdx.x >> 5;
    #pragma unroll
    for (int j = 0; j < 32; j += 8)
        t[ty + j][tx] = W[(size_t)(by + ty + j) * 1024 + bx + tx];
    __syncthreads();
    #pragma unroll
    for (int j = 0; j < 32; j += 8) {
        size_t o = (size_t)(bx + ty + j) * 1024 + by + tx;
        out[o] = __float2half_rn(t[tx][ty + j]);
    }
}

// ---------------------------------------------------------------------------
// Spatial attention: fp16 in, fp16 out, fp32 math
// ---------------------------------------------------------------------------
__global__ __launch_bounds__(64) void spatial_attn_kernel(
    const __half* __restrict__ Q, const __half* __restrict__ K,
    const __half* __restrict__ V, const int* __restrict__ mask,
    __half* __restrict__ O)
{
    __shared__ float sK[8][512];
    __shared__ float sV[8][512];
    int blk  = blockIdx.x;
    int half = blk & 1;
    int c    = (blk >> 1) & (NCq - 1);
    int b    = blk >> 9;
    size_t base = ((size_t)b * Sq + (size_t)c * CLIPq) * Dq;

    for (int idx = threadIdx.x; idx < 2048; idx += 64) {
        int r = idx >> 8, c2 = idx & 255;
        size_t g = base + (size_t)r * Dq + half * 512 + c2 * 2;
        float2 kf = __half22float2(*(const __half2*)&K[g]);
        float2 vf = __half22float2(*(const __half2*)&V[g]);
        sK[r][c2*2] = kf.x; sK[r][c2*2+1] = kf.y;
        sV[r][c2*2] = vf.x; sV[r][c2*2+1] = vf.y;
    }
    __syncthreads();

    int hp = threadIdx.x >> 3;
    int i  = threadIdx.x & 7;
    int h  = half * 8 + hp;

    float q[64];
    const __half* qg = &Q[base + (size_t)i * Dq + h * DKq];
    #pragma unroll
    for (int d = 0; d < 64; d += 2) {
        float2 t = __half22float2(*(const __half2*)&qg[d]);
        q[d] = t.x; q[d+1] = t.y;
    }

    float e[8]; float l = 0.f;
    #pragma unroll
    for (int j = 0; j < 8; j++) {
        const float* kr = &sK[j][hp * DKq];
        float s0 = 0.f, s1 = 0.f, s2 = 0.f, s3 = 0.f;
        #pragma unroll
        for (int d = 0; d < 64; d += 4) {
            s0 += q[d]   * kr[d];   s1 += q[d+1] * kr[d+1];
            s2 += q[d+2] * kr[d+2]; s3 += q[d+3] * kr[d+3];
        }
        float s = (s0 + s1 + s2 + s3) * 0.125f;
        float ee = mask[b * Sq + c * CLIPq + j] ? __expf(s) : 0.f;
        e[j] = ee; l += ee;
    }
    float inv = 1.f / l;

    float out[64];
    #pragma unroll
    for (int d = 0; d < 64; d++) out[d] = 0.f;
    #pragma unroll
    for (int j = 0; j < 8; j++) {
        const float* vr = &sV[j][hp * DKq];
        float ej = e[j];
        #pragma unroll
        for (int d = 0; d < 64; d++) out[d] += ej * vr[d];
    }

    size_t ob = base + (size_t)i * Dq + h * DKq;
    #pragma unroll
    for (int d = 0; d < 64; d += 2)
        *(__half2*)(O + ob + d) = __floats2half2_rn(out[d]*inv, out[d+1]*inv);
}

// ---------------------------------------------------------------------------
// Temporal attention, tensor cores.
// Unit = (b, clip-pos p, head h): 256x256 attention, dk=64, fp16 in/out.
// CTA = 128 query rows (8 warps x 16 rows); 2 CTAs per unit -> grid 4096.
// KV processed in 4 tiles of 64 keys. V staged transposed so both MMAs use
// the plain K-major ldmatrix B pattern. Softmax fp32, no max subtraction.
// ---------------------------------------------------------------------------
__global__ __launch_bounds__(256, 2) void temporal_attn_tc_kernel(
    const __half* __restrict__ Q, const __half* __restrict__ K,
    const __half* __restrict__ V, const int* __restrict__ mask,
    __half* __restrict__ O)
{
    __shared__ __half sQ[128 * 72];
    __shared__ __half sKt[64 * 72];
    __shared__ __half sVt[64 * 72];
    __shared__ float sMask[256];

    const int tid  = threadIdx.x;
    const int lane = tid & 31, w = tid >> 5;
    const int blk  = blockIdx.x;
    const int hh = blk & 1;
    const int h  = (blk >> 1) & 15;
    const int p  = (blk >> 5) & 7;
    const int b  = blk >> 8;

    const size_t ub = ((size_t)b * Sq + p) * Dq + h * DKq;  // + clip*8192

    if (tid < 256) sMask[tid] = mask[b * Sq + tid * CLIPq + p] ? 1.f : 0.f;

    // stage Q: 128 rows x 8 16B-chunks = 1024 items
    #pragma unroll
    for (int i = 0; i < 4; i++) {
        int idx = tid + i * 256;
        int r = idx >> 3, c = idx & 7;
        *(uint4*)&sQ[r * 72 + c * 8] =
            *(const uint4*)&Q[ub + (size_t)(hh * 128 + r) * (CLIPq * Dq) + c * 8];
    }
    __syncthreads();

    const uint32_t sQu = smem_u32(sQ);
    const uint32_t sKu = smem_u32(sKt);
    const uint32_t sVu = smem_u32(sVt);
    const int rowB = (lane & 7) + (lane >> 4) * 8;
    const int kbB  = ((lane >> 3) & 1) * 16;
    const int c4   = lane & 3, r4 = lane >> 2;

    // Q fragments: M=16 per warp, 4 k16 steps
    uint32_t qf[4][4];
    {
        uint32_t qb = sQu + ((w * 16 + (lane & 15)) * 72) * 2 + (lane >> 4) * 16;
        #pragma unroll
        for (int ks = 0; ks < 4; ks++) ldsm4(qf[ks], qb + ks * 32);
    }

    float oacc[8][4];
    #pragma unroll
    for (int i = 0; i < 8; i++)
        #pragma unroll
        for (int j = 0; j < 4; j++) oacc[i][j] = 0.f;
    float lLow = 0.f, lHigh = 0.f;

    for (int t = 0; t < 4; t++) {
        // stage K tile [key][d] and V^T tile [d][key]: 64 rows x 8 chunks
        #pragma unroll
        for (int i = 0; i < 2; i++) {
            int idx = tid + i * 256;
            int r = idx >> 3, c = idx & 7;
            size_t src = ub + (size_t)(t * 64 + r) * (CLIPq * Dq) + c * 8;
            *(uint4*)&sKt[r * 72 + c * 8] = *(const uint4*)&K[src];
            uint4 v = *(const uint4*)&V[src];
            const __half* vh = (const __half*)&v;
            #pragma unroll
            for (int j = 0; j < 8; j++)
                sVt[(c * 8 + j) * 72 + r] = vh[j];
        }
        __syncthreads();

        // S = Q K^T
        float sacc[8][4];
        #pragma unroll
        for (int i = 0; i < 8; i++)
            #pragma unroll
            for (int j = 0; j < 4; j++) sacc[i][j] = 0.f;

        #pragma unroll
        for (int ks = 0; ks < 4; ks++) {
            uint32_t kf[4][4];
            #pragma unroll
            for (int pp = 0; pp < 4; pp++)
                ldsm4(kf[pp], sKu + ((pp * 16 + rowB) * 72) * 2 + kbB + ks * 32);
            #pragma unroll
            for (int nt = 0; nt < 8; nt++)
                mma_f16(sacc[nt], qf[ks], kf[nt >> 1][(nt & 1) * 2],
                        kf[nt >> 1][(nt & 1) * 2 + 1]);
        }

        // softmax numerators (fp32), masked; row partial sums
        float psumL = 0.f, psumH = 0.f;
        #pragma unroll
        for (int nt = 0; nt < 8; nt++) {
            int k0 = t * 64 + nt * 8 + c4 * 2;
            float m0 = sMask[k0], m1 = sMask[k0 + 1];
            sacc[nt][0] = __expf(sacc[nt][0] * 0.125f) * m0;
            sacc[nt][1] = __expf(sacc[nt][1] * 0.125f) * m1;
            sacc[nt][2] = __expf(sacc[nt][2] * 0.125f) * m0;
            sacc[nt][3] = __expf(sacc[nt][3] * 0.125f) * m1;
            psumL += sacc[nt][0] + sacc[nt][1];
            psumH += sacc[nt][2] + sacc[nt][3];
        }
        psumL += __shfl_xor_sync(0xFFFFFFFFu, psumL, 1);
        psumL += __shfl_xor_sync(0xFFFFFFFFu, psumL, 2);
        psumH += __shfl_xor_sync(0xFFFFFFFFu, psumH, 1);
        psumH += __shfl_xor_sync(0xFFFFFFFFu, psumH, 2);
        lLow += psumL; lHigh += psumH;

        // O += P V   (P from registers via acc->A relayout)
        #pragma unroll
        for (int j = 0; j < 4; j++) {
            uint32_t pa[4];
            pa[0] = packh2(sacc[2*j][0],   sacc[2*j][1]);
            pa[1] = packh2(sacc[2*j][2],   sacc[2*j][3]);
            pa[2] = packh2(sacc[2*j+1][0], sacc[2*j+1][1]);
            pa[3] = packh2(sacc[2*j+1][2], sacc[2*j+1][3]);
            uint32_t vf[4][4];
            #pragma unroll
            for (int pd = 0; pd < 4; pd++)
                ldsm4(vf[pd], sVu + ((pd * 16 + rowB) * 72) * 2 + kbB + j * 32);
            #pragma unroll
            for (int nd = 0; nd < 8; nd++)
                mma_f16(oacc[nd], pa, vf[nd >> 1][(nd & 1) * 2],
                        vf[nd >> 1][(nd & 1) * 2 + 1]);
        }
        __syncthreads();
    }

    // normalize + write
    float invL = 1.f / lLow, invH = 1.f / lHigh;
    int cqL = hh * 128 + w * 16 + r4;
    size_t rowL = ((size_t)b * Sq + (size_t)cqL * CLIPq + p) * Dq + h * DKq;
    size_t rowH = rowL + (size_t)8 * CLIPq * Dq;
    #pragma unroll
    for (int nd = 0; nd < 8; nd++) {
        int d0 = nd * 8 + c4 * 2;
        *(__half2*)&O[rowL + d0] =
            __floats2half2_rn(oacc[nd][0] * invL, oacc[nd][1] * invL);
        *(__half2*)&O[rowH + d0] =
            __floats2half2_rn(oacc[nd][2] * invH, oacc[nd][3] * invH);
    }
}

// ---------------------------------------------------------------------------
// Launch
// ---------------------------------------------------------------------------
extern "C" void kernel_launch(void* const* d_in, const int* in_sizes, int n_in,
                              void* d_out, int out_size)
{
    const float* x      = (const float*)d_in[0];
    const int*   mask   = (const int*)  d_in[1];
    const float* wsrc[10] = {
        (const float*)d_in[2],  (const float*)d_in[4],
        (const float*)d_in[6],  (const float*)d_in[8],
        (const float*)d_in[10], (const float*)d_in[12],
        (const float*)d_in[14], (const float*)d_in[16],
        (const float*)d_in[18],
        (const float*)d_in[18] + (size_t)1024 * 1024
    };
    const float* sa_q_b = (const float*)d_in[3];
    const float* sa_k_b = (const float*)d_in[5];
    const float* sa_v_b = (const float*)d_in[7];
    const float* sa_o_b = (const float*)d_in[9];
    const float* ta_q_b = (const float*)d_in[11];
    const float* ta_k_b = (const float*)d_in[13];
    const float* ta_v_b = (const float*)d_in[15];
    const float* ta_o_b = (const float*)d_in[17];
    const float* fuse_b = (const float*)d_in[19];
    float* out = (float*)d_out;

    float* base = nullptr;
    cudaGetSymbolAddress((void**)&base, g_buf);
    __half* pool = (__half*)base;
    __half* qH = pool;
    __half* kH = pool + NELEM;
    __half* vH = pool + 2*NELEM;
    __half* aH = pool + 3*NELEM;
    __half* sH = pool + 4*NELEM;
    __half* tH = pool + 5*NELEM;
    __half* xH = pool + 6*NELEM;
    __half* wH = pool + 7*NELEM;

    cudaFuncSetAttribute(tcgemm_kernel,
        cudaFuncAttributeMaxDynamicSharedMemorySize, TC_SMEM);

    const int n4 = (int)(NELEM / 4);
    const int convBlocks = (n4 + 255) / 256;
    dim3 tgrid(32, 32), tblk(256);
    dim3 ggrid(Dq / 128, NTOK / 128);   // (8, 256)

    conv_kernel<<<convBlocks, 256>>>(x, xH, n4);
    for (int i = 0; i < 10; i++)
        transpose_h_kernel<<<tgrid, tblk>>>(wsrc[i], wH + (size_t)i * 1024 * 1024);

    #define WT(i) (wH + (size_t)(i)*1024*1024)
    #define NOH   (__half*)nullptr

    // Spatial branch
    tcgemm_kernel<<<ggrid, 256, TC_SMEM>>>(xH, WT(0), sa_q_b, nullptr, qH, 0);
    tcgemm_kernel<<<ggrid, 256, TC_SMEM>>>(xH, WT(1), sa_k_b, nullptr, kH, 0);
    tcgemm_kernel<<<ggrid, 256, TC_SMEM>>>(xH, WT(2), sa_v_b, nullptr, vH, 0);
    spatial_attn_kernel<<<Bq*NCq*2, 64>>>(qH, kH, vH, mask, aH);
    tcgemm_kernel<<<ggrid, 256, TC_SMEM>>>(aH, WT(3), sa_o_b, nullptr, sH, 0);

    // Temporal branch
    tcgemm_kernel<<<ggrid, 256, TC_SMEM>>>(xH, WT(4), ta_q_b, nullptr, qH, 0);
    tcgemm_kernel<<<ggrid, 256, TC_SMEM>>>(xH, WT(5), ta_k_b, nullptr, kH, 0);
    tcgemm_kernel<<<ggrid, 256, TC_SMEM>>>(xH, WT(6), ta_v_b, nullptr, vH, 0);
    temporal_attn_tc_kernel<<<4096, 256>>>(qH, kH, vH, mask, aH);
    tcgemm_kernel<<<ggrid, 256, TC_SMEM>>>(aH, WT(7), ta_o_b, nullptr, tH, 0);

    // Fuse
    tcgemm_kernel<<<ggrid, 256, TC_SMEM>>>(sH, WT(8), fuse_b, out, NOH, 0);
    tcgemm_kernel<<<ggrid, 256, TC_SMEM>>>(tH, WT(9), nullptr, out, NOH, 1);
}

// round 11
// speedup vs baseline: 5.6633x; 1.0111x over previous
#include <cuda_runtime.h>
#include <cuda_fp16.h>
#include <cstdint>

// Problem constants
#define Bq    16
#define Sq    2048
#define Dq    1024
#define Hq    16
#define CLIPq 8
#define NCq   256
#define DKq   64
#define NTOK  (Bq*Sq)                 // 32768 tokens
#define NELEM ((size_t)NTOK*Dq)       // 33554432 elems per (B,S,D) buffer

// Scratch pool: all-fp16 activations.
__device__ float g_buf[6ull*33554432ull];

__device__ __forceinline__ uint32_t smem_u32(const void* p) {
    uint32_t a;
    asm("{ .reg .u64 t; cvta.to.shared.u64 t, %1; cvt.u32.u64 %0, t; }"
        : "=r"(a) : "l"(p));
    return a;
}

__device__ __forceinline__ void ldsm4(uint32_t* r, uint32_t a) {
    asm volatile("ldmatrix.sync.aligned.m8n8.x4.shared.b16 {%0,%1,%2,%3}, [%4];"
        : "=r"(r[0]), "=r"(r[1]), "=r"(r[2]), "=r"(r[3]) : "r"(a));
}

__device__ __forceinline__ void mma_f16(float* c,
    const uint32_t* a, uint32_t b0, uint32_t b1) {
    asm volatile("mma.sync.aligned.m16n8k16.row.col.f32.f16.f16.f32 "
        "{%0,%1,%2,%3}, {%4,%5,%6,%7}, {%8,%9}, {%0,%1,%2,%3};"
        : "+f"(c[0]), "+f"(c[1]), "+f"(c[2]), "+f"(c[3])
        : "r"(a[0]), "r"(a[1]), "r"(a[2]), "r"(a[3]), "r"(b0), "r"(b1));
}

__device__ __forceinline__ void cp16(uint32_t s, const void* g) {
    asm volatile("cp.async.cg.shared.global [%0], [%1], 16;" :: "r"(s), "l"(g));
}

__device__ __forceinline__ uint32_t packh2(float x, float y) {
    __half2 h = __floats2half2_rn(x, y);
    return *(uint32_t*)&h;
}

// ============================================================================
// fp16 GEMM via mma.sync: C[M,N] = A[M,K] @ B^T[N,K] (+bias / +beta / fp16 out)
// CTA tile 128x256, warp tile 64x64 (8 warps, 2x4), BK=64, 3-stage cp.async.
// SMEM row stride 144B -> ldmatrix conflict-free. 1 CTA/SM.
// ============================================================================
#define GSTRIDE 144                       // bytes per 64-elem fp16 row (+pad)
#define GA_TILE (128 * GSTRIDE)           // 18432
#define GB_TILE (256 * GSTRIDE)           // 36864
#define GSTAGE  (GA_TILE + GB_TILE)       // 55296
#define TC_SMEM (3 * GSTAGE)              // 165888
#define GNIT    (Dq / 64)                 // 16

__global__ void __launch_bounds__(256, 1) tcgemm_kernel(
    const __half* __restrict__ A, const __half* __restrict__ B,
    const float* __restrict__ bias, float* __restrict__ C,
    __half* __restrict__ Ch, int beta)
{
    extern __shared__ char smem[];
    const uint32_t sb = smem_u32(smem);
    const int tid  = threadIdx.x;
    const int lane = tid & 31;
    const int wid  = tid >> 5;
    const int wm = (wid >> 2) * 64;       // 0 or 64
    const int wn = (wid & 3) * 64;        // 0,64,128,192
    const int bm = blockIdx.y * 128;
    const int bn = blockIdx.x * 256;
    const int K  = Dq;

    const __half* gA = A + (size_t)bm * K;
    const __half* gB = B + (size_t)bn * K;

    float acc[4][8][4];
    #pragma unroll
    for (int i = 0; i < 4; i++)
        #pragma unroll
        for (int j = 0; j < 8; j++)
            #pragma unroll
            for (int k = 0; k < 4; k++) acc[i][j][k] = 0.f;

    const int rowA = (lane & 7) + ((lane >> 3) & 1) * 8;
    const int kbA  = (lane >> 4) * 16;
    const int rowB = (lane & 7) + (lane >> 4) * 8;
    const int kbB  = ((lane >> 3) & 1) * 16;

    // fill one stage: A 128x8 chunks (1024) + B 256x8 chunks (2048)
    auto fill = [&](int it, int buf) {
        uint32_t sst = sb + buf * GSTAGE;
        int k0 = it * 64;
        #pragma unroll
        for (int j = 0; j < 4; j++) {
            int idx = tid + j * 256;             // 0..1023
            int r = idx >> 3, c = idx & 7;
            cp16(sst + r * GSTRIDE + c * 16, gA + (size_t)r * K + k0 + c * 8);
        }
        #pragma unroll
        for (int j = 0; j < 8; j++) {
            int idx = tid + j * 256;             // 0..2047
            int r = idx >> 3, c = idx & 7;
            cp16(sst + GA_TILE + r * GSTRIDE + c * 16,
                 gB + (size_t)r * K + k0 + c * 8);
        }
        asm volatile("cp.async.commit_group;" ::: "memory");
    };

    fill(0, 0);
    fill(1, 1);

    int buf = 0;
    for (int it = 0; it < GNIT; it++) {
        if (it + 2 < GNIT) {
            fill(it + 2, (it + 2) % 3);
            asm volatile("cp.async.wait_group 2;" ::: "memory");
        } else if (it + 1 < GNIT) {
            asm volatile("cp.async.wait_group 1;" ::: "memory");
        } else {
            asm volatile("cp.async.wait_group 0;" ::: "memory");
        }
        __syncthreads();

        uint32_t sst = sb + buf * GSTAGE;
        uint32_t aB = sst + (wm + rowA) * GSTRIDE + kbA;
        uint32_t bB = sst + GA_TILE + (wn + rowB) * GSTRIDE + kbB;

        #pragma unroll
        for (int ks = 0; ks < 4; ks++) {
            uint32_t a[4][4], b[4][4];
            #pragma unroll
            for (int mt = 0; mt < 4; mt++)
                ldsm4(a[mt], aB + mt * 16 * GSTRIDE + ks * 32);
            #pragma unroll
            for (int p = 0; p < 4; p++)
                ldsm4(b[p], bB + p * 16 * GSTRIDE + ks * 32);
            #pragma unroll
            for (int mt = 0; mt < 4; mt++)
                #pragma unroll
                for (int nt = 0; nt < 8; nt++)
                    mma_f16(acc[mt][nt], a[mt], b[nt >> 1][(nt & 1) * 2],
                            b[nt >> 1][(nt & 1) * 2 + 1]);
        }
        __syncthreads();
        buf = (buf + 1) % 3;
    }

    // Epilogue
    #pragma unroll
    for (int mt = 0; mt < 4; mt++) {
        #pragma unroll
        for (int nt = 0; nt < 8; nt++) {
            int r0 = bm + wm + mt * 16 + (lane >> 2);
            int c0 = bn + wn + nt * 8 + (lane & 3) * 2;
            #pragma unroll
            for (int hrow = 0; hrow < 2; hrow++) {
                float vx = acc[mt][nt][hrow * 2];
                float vy = acc[mt][nt][hrow * 2 + 1];
                if (bias) {
                    vx += __ldg(&bias[c0]);
                    vy += __ldg(&bias[c0 + 1]);
                }
                size_t off = (size_t)(r0 + hrow * 8) * Dq + c0;
                if (Ch) {
                    *(__half2*)(Ch + off) = __floats2half2_rn(vx, vy);
                } else {
                    float* cp = C + off;
                    if (beta) {
                        float2 o = *(float2*)cp;
                        vx += o.x; vy += o.y;
                    }
                    *(float2*)cp = make_float2(vx, vy);
                }
            }
        }
    }
}

// ============================================================================
// fp32 -> fp16 convert (x only)
// ============================================================================
__global__ void __launch_bounds__(256) conv_kernel(
    const float* __restrict__ in, __half* __restrict__ out, int n4)
{
    int i = blockIdx.x * 256 + threadIdx.x;
    if (i >= n4) return;
    float4 v = ((const float4*)in)[i];
    ((__half2*)out)[i * 2]     = __floats2half2_rn(v.x, v.y);
    ((__half2*)out)[i * 2 + 1] = __floats2half2_rn(v.z, v.w);
}

// ============================================================================
// Weight transpose + fp16
// ============================================================================
__global__ void __launch_bounds__(256) transpose_h_kernel(
    const float* __restrict__ W, __half* __restrict__ out)
{
    __shared__ float t[32][33];
    int bx = blockIdx.x * 32, by = blockIdx.y * 32;
    int tx = threadIdx.x & 31, ty = threadIdx.x >> 5;
    #pragma unroll
    for (int j = 0; j < 32; j += 8)
        t[ty + j][tx] = W[(size_t)(by + ty + j) * 1024 + bx + tx];
    __syncthreads();
    #pragma unroll
    for (int j = 0; j < 32; j += 8) {
        size_t o = (size_t)(bx + ty + j) * 1024 + by + tx;
        out[o] = __float2half_rn(t[tx][ty + j]);
    }
}

// ---------------------------------------------------------------------------
// Spatial attention: fp16 in, fp16 out, fp32 math
// ---------------------------------------------------------------------------
__global__ __launch_bounds__(64) void spatial_attn_kernel(
    const __half* __restrict__ Q, const __half* __restrict__ K,
    const __half* __restrict__ V, const int* __restrict__ mask,
    __half* __restrict__ O)
{
    __shared__ float sK[8][512];
    __shared__ float sV[8][512];
    int blk  = blockIdx.x;
    int half = blk & 1;
    int c    = (blk >> 1) & (NCq - 1);
    int b    = blk >> 9;
    size_t base = ((size_t)b * Sq + (size_t)c * CLIPq) * Dq;

    for (int idx = threadIdx.x; idx < 2048; idx += 64) {
        int r = idx >> 8, c2 = idx & 255;
        size_t g = base + (size_t)r * Dq + half * 512 + c2 * 2;
        float2 kf = __half22float2(*(const __half2*)&K[g]);
        float2 vf = __half22float2(*(const __half2*)&V[g]);
        sK[r][c2*2] = kf.x; sK[r][c2*2+1] = kf.y;
        sV[r][c2*2] = vf.x; sV[r][c2*2+1] = vf.y;
    }
    __syncthreads();

    int hp = threadIdx.x >> 3;
    int i  = threadIdx.x & 7;
    int h  = half * 8 + hp;

    float q[64];
    const __half* qg = &Q[base + (size_t)i * Dq + h * DKq];
    #pragma unroll
    for (int d = 0; d < 64; d += 2) {
        float2 t = __half22float2(*(const __half2*)&qg[d]);
        q[d] = t.x; q[d+1] = t.y;
    }

    float e[8]; float l = 0.f;
    #pragma unroll
    for (int j = 0; j < 8; j++) {
        const float* kr = &sK[j][hp * DKq];
        float s0 = 0.f, s1 = 0.f, s2 = 0.f, s3 = 0.f;
        #pragma unroll
        for (int d = 0; d < 64; d += 4) {
            s0 += q[d]   * kr[d];   s1 += q[d+1] * kr[d+1];
            s2 += q[d+2] * kr[d+2]; s3 += q[d+3] * kr[d+3];
        }
        float s = (s0 + s1 + s2 + s3) * 0.125f;
        float ee = mask[b * Sq + c * CLIPq + j] ? __expf(s) : 0.f;
        e[j] = ee; l += ee;
    }
    float inv = 1.f / l;

    float out[64];
    #pragma unroll
    for (int d = 0; d < 64; d++) out[d] = 0.f;
    #pragma unroll
    for (int j = 0; j < 8; j++) {
        const float* vr = &sV[j][hp * DKq];
        float ej = e[j];
        #pragma unroll
        for (int d = 0; d < 64; d++) out[d] += ej * vr[d];
    }

    size_t ob = base + (size_t)i * Dq + h * DKq;
    #pragma unroll
    for (int d = 0; d < 64; d += 2)
        *(__half2*)(O + ob + d) = __floats2half2_rn(out[d]*inv, out[d+1]*inv);
}

// ---------------------------------------------------------------------------
// Temporal attention, tensor cores (validated in R9)
// ---------------------------------------------------------------------------
__global__ __launch_bounds__(256, 2) void temporal_attn_tc_kernel(
    const __half* __restrict__ Q, const __half* __restrict__ K,
    const __half* __restrict__ V, const int* __restrict__ mask,
    __half* __restrict__ O)
{
    __shared__ __half sQ[128 * 72];
    __shared__ __half sKt[64 * 72];
    __shared__ __half sVt[64 * 72];
    __shared__ float sMask[256];

    const int tid  = threadIdx.x;
    const int lane = tid & 31, w = tid >> 5;
    const int blk  = blockIdx.x;
    const int hh = blk & 1;
    const int h  = (blk >> 1) & 15;
    const int p  = (blk >> 5) & 7;
    const int b  = blk >> 8;

    const size_t ub = ((size_t)b * Sq + p) * Dq + h * DKq;

    if (tid < 256) sMask[tid] = mask[b * Sq + tid * CLIPq + p] ? 1.f : 0.f;

    #pragma unroll
    for (int i = 0; i < 4; i++) {
        int idx = tid + i * 256;
        int r = idx >> 3, c = idx & 7;
        *(uint4*)&sQ[r * 72 + c * 8] =
            *(const uint4*)&Q[ub + (size_t)(hh * 128 + r) * (CLIPq * Dq) + c * 8];
    }
    __syncthreads();

    const uint32_t sQu = smem_u32(sQ);
    const uint32_t sKu = smem_u32(sKt);
    const uint32_t sVu = smem_u32(sVt);
    const int rowB = (lane & 7) + (lane >> 4) * 8;
    const int kbB  = ((lane >> 3) & 1) * 16;
    const int c4   = lane & 3, r4 = lane >> 2;

    uint32_t qf[4][4];
    {
        uint32_t qb = sQu + ((w * 16 + (lane & 15)) * 72) * 2 + (lane >> 4) * 16;
        #pragma unroll
        for (int ks = 0; ks < 4; ks++) ldsm4(qf[ks], qb + ks * 32);
    }

    float oacc[8][4];
    #pragma unroll
    for (int i = 0; i < 8; i++)
        #pragma unroll
        for (int j = 0; j < 4; j++) oacc[i][j] = 0.f;
    float lLow = 0.f, lHigh = 0.f;

    for (int t = 0; t < 4; t++) {
        #pragma unroll
        for (int i = 0; i < 2; i++) {
            int idx = tid + i * 256;
            int r = idx >> 3, c = idx & 7;
            size_t src = ub + (size_t)(t * 64 + r) * (CLIPq * Dq) + c * 8;
            *(uint4*)&sKt[r * 72 + c * 8] = *(const uint4*)&K[src];
            uint4 v = *(const uint4*)&V[src];
            const __half* vh = (const __half*)&v;
            #pragma unroll
            for (int j = 0; j < 8; j++)
                sVt[(c * 8 + j) * 72 + r] = vh[j];
        }
        __syncthreads();

        float sacc[8][4];
        #pragma unroll
        for (int i = 0; i < 8; i++)
            #pragma unroll
            for (int j = 0; j < 4; j++) sacc[i][j] = 0.f;

        #pragma unroll
        for (int ks = 0; ks < 4; ks++) {
            uint32_t kf[4][4];
            #pragma unroll
            for (int pp = 0; pp < 4; pp++)
                ldsm4(kf[pp], sKu + ((pp * 16 + rowB) * 72) * 2 + kbB + ks * 32);
            #pragma unroll
            for (int nt = 0; nt < 8; nt++)
                mma_f16(sacc[nt], qf[ks], kf[nt >> 1][(nt & 1) * 2],
                        kf[nt >> 1][(nt & 1) * 2 + 1]);
        }

        float psumL = 0.f, psumH = 0.f;
        #pragma unroll
        for (int nt = 0; nt < 8; nt++) {
            int k0 = t * 64 + nt * 8 + c4 * 2;
            float m0 = sMask[k0], m1 = sMask[k0 + 1];
            sacc[nt][0] = __expf(sacc[nt][0] * 0.125f) * m0;
            sacc[nt][1] = __expf(sacc[nt][1] * 0.125f) * m1;
            sacc[nt][2] = __expf(sacc[nt][2] * 0.125f) * m0;
            sacc[nt][3] = __expf(sacc[nt][3] * 0.125f) * m1;
            psumL += sacc[nt][0] + sacc[nt][1];
            psumH += sacc[nt][2] + sacc[nt][3];
        }
        psumL += __shfl_xor_sync(0xFFFFFFFFu, psumL, 1);
        psumL += __shfl_xor_sync(0xFFFFFFFFu, psumL, 2);
        psumH += __shfl_xor_sync(0xFFFFFFFFu, psumH, 1);
        psumH += __shfl_xor_sync(0xFFFFFFFFu, psumH, 2);
        lLow += psumL; lHigh += psumH;

        #pragma unroll
        for (int j = 0; j < 4; j++) {
            uint32_t pa[4];
            pa[0] = packh2(sacc[2*j][0],   sacc[2*j][1]);
            pa[1] = packh2(sacc[2*j][2],   sacc[2*j][3]);
            pa[2] = packh2(sacc[2*j+1][0], sacc[2*j+1][1]);
            pa[3] = packh2(sacc[2*j+1][2], sacc[2*j+1][3]);
            uint32_t vf[4][4];
            #pragma unroll
            for (int pd = 0; pd < 4; pd++)
                ldsm4(vf[pd], sVu + ((pd * 16 + rowB) * 72) * 2 + kbB + j * 32);
            #pragma unroll
            for (int nd = 0; nd < 8; nd++)
                mma_f16(oacc[nd], pa, vf[nd >> 1][(nd & 1) * 2],
                        vf[nd >> 1][(nd & 1) * 2 + 1]);
        }
        __syncthreads();
    }

    float invL = 1.f / lLow, invH = 1.f / lHigh;
    int cqL = hh * 128 + w * 16 + r4;
    size_t rowL = ((size_t)b * Sq + (size_t)cqL * CLIPq + p) * Dq + h * DKq;
    size_t rowH = rowL + (size_t)8 * CLIPq * Dq;
    #pragma unroll
    for (int nd = 0; nd < 8; nd++) {
        int d0 = nd * 8 + c4 * 2;
        *(__half2*)&O[rowL + d0] =
            __floats2half2_rn(oacc[nd][0] * invL, oacc[nd][1] * invL);
        *(__half2*)&O[rowH + d0] =
            __floats2half2_rn(oacc[nd][2] * invH, oacc[nd][3] * invH);
    }
}

// ---------------------------------------------------------------------------
// Launch
// ---------------------------------------------------------------------------
extern "C" void kernel_launch(void* const* d_in, const int* in_sizes, int n_in,
                              void* d_out, int out_size)
{
    const float* x      = (const float*)d_in[0];
    const int*   mask   = (const int*)  d_in[1];
    const float* wsrc[10] = {
        (const float*)d_in[2],  (const float*)d_in[4],
        (const float*)d_in[6],  (const float*)d_in[8],
        (const float*)d_in[10], (const float*)d_in[12],
        (const float*)d_in[14], (const float*)d_in[16],
        (const float*)d_in[18],
        (const float*)d_in[18] + (size_t)1024 * 1024
    };
    const float* sa_q_b = (const float*)d_in[3];
    const float* sa_k_b = (const float*)d_in[5];
    const float* sa_v_b = (const float*)d_in[7];
    const float* sa_o_b = (const float*)d_in[9];
    const float* ta_q_b = (const float*)d_in[11];
    const float* ta_k_b = (const float*)d_in[13];
    const float* ta_v_b = (const float*)d_in[15];
    const float* ta_o_b = (const float*)d_in[17];
    const float* fuse_b = (const float*)d_in[19];
    float* out = (float*)d_out;

    float* base = nullptr;
    cudaGetSymbolAddress((void**)&base, g_buf);
    __half* pool = (__half*)base;
    __half* qH = pool;
    __half* kH = pool + NELEM;
    __half* vH = pool + 2*NELEM;
    __half* aH = pool + 3*NELEM;
    __half* sH = pool + 4*NELEM;
    __half* tH = pool + 5*NELEM;
    __half* xH = pool + 6*NELEM;
    __half* wH = pool + 7*NELEM;

    cudaFuncSetAttribute(tcgemm_kernel,
        cudaFuncAttributeMaxDynamicSharedMemorySize, TC_SMEM);

    const int n4 = (int)(NELEM / 4);
    const int convBlocks = (n4 + 255) / 256;
    dim3 tgrid(32, 32), tblk(256);
    dim3 ggrid(Dq / 256, NTOK / 128);   // (4, 256)

    conv_kernel<<<convBlocks, 256>>>(x, xH, n4);
    for (int i = 0; i < 10; i++)
        transpose_h_kernel<<<tgrid, tblk>>>(wsrc[i], wH + (size_t)i * 1024 * 1024);

    #define WT(i) (wH + (size_t)(i)*1024*1024)
    #define NOH   (__half*)nullptr

    // Spatial branch
    tcgemm_kernel<<<ggrid, 256, TC_SMEM>>>(xH, WT(0), sa_q_b, nullptr, qH, 0);
    tcgemm_kernel<<<ggrid, 256, TC_SMEM>>>(xH, WT(1), sa_k_b, nullptr, kH, 0);
    tcgemm_kernel<<<ggrid, 256, TC_SMEM>>>(xH, WT(2), sa_v_b, nullptr, vH, 0);
    spatial_attn_kernel<<<Bq*NCq*2, 64>>>(qH, kH, vH, mask, aH);
    tcgemm_kernel<<<ggrid, 256, TC_SMEM>>>(aH, WT(3), sa_o_b, nullptr, sH, 0);

    // Temporal branch
    tcgemm_kernel<<<ggrid, 256, TC_SMEM>>>(xH, WT(4), ta_q_b, nullptr, qH, 0);
    tcgemm_kernel<<<ggrid, 256, TC_SMEM>>>(xH, WT(5), ta_k_b, nullptr, kH, 0);
    tcgemm_kernel<<<ggrid, 256, TC_SMEM>>>(xH, WT(6), ta_v_b, nullptr, vH, 0);
    temporal_attn_tc_kernel<<<4096, 256>>>(qH, kH, vH, mask, aH);
    tcgemm_kernel<<<ggrid, 256, TC_SMEM>>>(aH, WT(7), ta_o_b, nullptr, tH, 0);

    // Fuse
    tcgemm_kernel<<<ggrid, 256, TC_SMEM>>>(sH, WT(8), fuse_b, out, NOH, 0);
    tcgemm_kernel<<<ggrid, 256, TC_SMEM>>>(tH, WT(9), nullptr, out, NOH, 1);
}